// round 15
// baseline (speedup 1.0000x reference)
#include <cuda_runtime.h>
#include <cuda_bf16.h>
#include <math.h>
#include <stdint.h>

#define B_  64
#define T_  20
#define H_  512
#define E_  512
#define V_  32000
#define NN_ 8192
#define G4  2048   // 4*H
#define NB  148    // total grid
#define NW  128    // worker CTAs participating in barriers
#define NQT 5000   // logits tiles: 20 steps x 250 col-tiles of 128

// ---------------- static scratch (no allocations allowed) ----------------
__device__ float d_node_proj[NN_ * H_];
__device__ float d_embpart[T_ * B_ * G4];
__device__ float d_hist[B_ * T_ * H_];
__device__ float d_c0[B_ * H_];
__device__ float d_c1[B_ * H_];
__device__ float d_bs0[G4];
__device__ float d_bs1[G4];
__device__ int   d_gidx[T_ * B_];

__device__ __nv_bfloat16 d_Wah[H_ * H_], d_Wal[H_ * H_];
__device__ __nv_bfloat16 d_W0h[G4 * 1024], d_W0l[G4 * 1024];
__device__ __nv_bfloat16 d_W1h[G4 * 1024], d_W1l[G4 * 1024];
__device__ __nv_bfloat16 d_xah[B_ * 1024], d_xal[B_ * 1024];
__device__ __nv_bfloat16 d_xbh[B_ * 1024], d_xbl[B_ * 1024];

__device__ float d_hppart[8 * B_ * H_];
__device__ float d_gpart0[4 * B_ * G4];
__device__ float d_gpart1[4 * B_ * G4];
__device__ unsigned g_cnt;    // barrier arrivals (128 workers x 6/step)
__device__ int d_qhead;       // logits tile queue head

// ===================== helpers =====================
__device__ __forceinline__ uint32_t smem_u32(const void* p) {
    uint32_t a;
    asm("{ .reg .u64 t; cvta.to.shared.u64 t, %1; cvt.u32.u64 %0, t; }"
        : "=r"(a) : "l"(p));
    return a;
}
__device__ __forceinline__ void ldsm4(uint32_t* r, uint32_t addr) {
    asm volatile("ldmatrix.sync.aligned.m8n8.x4.shared.b16 {%0,%1,%2,%3}, [%4];"
                 : "=r"(r[0]), "=r"(r[1]), "=r"(r[2]), "=r"(r[3]) : "r"(addr));
}
__device__ __forceinline__ void ldsm2(uint32_t* r, uint32_t addr) {
    asm volatile("ldmatrix.sync.aligned.m8n8.x2.shared.b16 {%0,%1}, [%2];"
                 : "=r"(r[0]), "=r"(r[1]) : "r"(addr));
}
__device__ __forceinline__ void mma_bf16(float* d, const uint32_t* a, const uint32_t* b) {
    asm volatile(
        "mma.sync.aligned.m16n8k16.row.col.f32.bf16.bf16.f32 "
        "{%0,%1,%2,%3}, {%4,%5,%6,%7}, {%8,%9}, {%0,%1,%2,%3};"
        : "+f"(d[0]), "+f"(d[1]), "+f"(d[2]), "+f"(d[3])
        : "r"(a[0]), "r"(a[1]), "r"(a[2]), "r"(a[3]), "r"(b[0]), "r"(b[1]));
}
__device__ __forceinline__ unsigned ldvol(const unsigned* p) {
    unsigned v;
    asm volatile("ld.global.cg.u32 %0, [%1];" : "=r"(v) : "l"(p) : "memory");
    return v;
}
__device__ __forceinline__ void split1(float v, __nv_bfloat16& h, __nv_bfloat16& l) {
    h = __float2bfloat16(v);
    l = __float2bfloat16(v - __bfloat162float(h));
}
__device__ __forceinline__ void split4(float4 a, uint2& hi, uint2& lo) {
    __nv_bfloat16 h0, h1, h2, h3, l0, l1, l2, l3;
    split1(a.x, h0, l0); split1(a.y, h1, l1);
    split1(a.z, h2, l2); split1(a.w, h3, l3);
    __nv_bfloat162 ph = __nv_bfloat162(h0, h1), qh = __nv_bfloat162(h2, h3);
    __nv_bfloat162 pl = __nv_bfloat162(l0, l1), ql = __nv_bfloat162(l2, l3);
    hi = make_uint2(*(uint32_t*)&ph, *(uint32_t*)&qh);
    lo = make_uint2(*(uint32_t*)&pl, *(uint32_t*)&ql);
}
__device__ __forceinline__ float sigf(float x) { return 1.f / (1.f + expf(-x)); }

// ========== big split-bf16 HMMA GEMM (validated R3/R4) ===================
#define TG_STAGE 40960
#define TG_SMEM  (2 * TG_STAGE)

__global__ void __launch_bounds__(256, 1) tgemm(
    const float* __restrict__ A, int lda,
    const float* __restrict__ Bw, int ldb,
    float* __restrict__ C, int ldc,
    const float* __restrict__ bias,
    int K, const int* __restrict__ gidx)
{
    extern __shared__ char sm[];
    const uint32_t sbase = smem_u32(sm);
    const int tid = threadIdx.x;
    const int lane = tid & 31, wid = tid >> 5;
    const int wm = wid & 1, wn = wid >> 1;
    const int m0 = blockIdx.x * 128, n0 = blockIdx.y * 128;
    const int lrow = tid >> 3;
    const int c4 = (tid & 7) << 2;
    const uint32_t aLane = (((uint32_t)(lane & 15) * 40u) + ((lane >> 4) * 8u)) * 2u;
    const uint32_t bLane = (((uint32_t)(lane & 7) * 40u) + (((lane >> 3) & 1) * 8u)) * 2u;

    float acc[4][4][4];
#pragma unroll
    for (int i = 0; i < 4; i++)
#pragma unroll
        for (int j = 0; j < 4; j++)
#pragma unroll
            for (int q = 0; q < 4; q++) acc[i][j][q] = 0.f;

    const int nch = K >> 5;
    float4 ga[4], gb[4];
#pragma unroll
    for (int v = 0; v < 4; v++) {
        int row = lrow + v * 32;
        int gr = gidx ? gidx[m0 + row] : (m0 + row);
        ga[v] = *(const float4*)(A + (size_t)gr * lda + c4);
        gb[v] = *(const float4*)(Bw + (size_t)(n0 + row) * ldb + c4);
    }
#pragma unroll
    for (int v = 0; v < 4; v++) {
        int row = lrow + v * 32;
        uint32_t off = ((uint32_t)row * 40u + (uint32_t)c4) * 2u;
        uint2 hi, lo;
        split4(ga[v], hi, lo);
        *(uint2*)(sm + off) = hi;
        *(uint2*)(sm + 10240 + off) = lo;
        split4(gb[v], hi, lo);
        *(uint2*)(sm + 20480 + off) = hi;
        *(uint2*)(sm + 30720 + off) = lo;
    }
    __syncthreads();

    for (int ich = 0; ich < nch; ich++) {
        const bool pf = (ich + 1 < nch);
        if (pf) {
            const int kb = (ich + 1) << 5;
#pragma unroll
            for (int v = 0; v < 4; v++) {
                int row = lrow + v * 32;
                int gr = gidx ? gidx[m0 + row] : (m0 + row);
                ga[v] = *(const float4*)(A + (size_t)gr * lda + kb + c4);
                gb[v] = *(const float4*)(Bw + (size_t)(n0 + row) * ldb + kb + c4);
            }
        }
        const uint32_t st = sbase + (uint32_t)(ich & 1) * TG_STAGE;
#pragma unroll
        for (int kk = 0; kk < 2; kk++) {
            uint32_t Ah[4][4], Al[4][4], Bh[4][2], Bl[4][2];
#pragma unroll
            for (int ma = 0; ma < 4; ma++) {
                uint32_t ad = st + (uint32_t)(wm * 64 + ma * 16) * 80u + aLane + kk * 32u;
                ldsm4(Ah[ma], ad);
                ldsm4(Al[ma], ad + 10240u);
            }
#pragma unroll
            for (int na = 0; na < 4; na++) {
                uint32_t bd = st + 20480u + (uint32_t)(wn * 32 + na * 8) * 80u + bLane + kk * 32u;
                ldsm2(Bh[na], bd);
                ldsm2(Bl[na], bd + 10240u);
            }
#pragma unroll
            for (int ma = 0; ma < 4; ma++)
#pragma unroll
                for (int na = 0; na < 4; na++) {
                    mma_bf16(acc[ma][na], Ah[ma], Bh[na]);
                    mma_bf16(acc[ma][na], Al[ma], Bh[na]);
                    mma_bf16(acc[ma][na], Ah[ma], Bl[na]);
                }
        }
        if (pf) {
            char* dstS = sm + ((ich + 1) & 1) * TG_STAGE;
#pragma unroll
            for (int v = 0; v < 4; v++) {
                int row = lrow + v * 32;
                uint32_t off = ((uint32_t)row * 40u + (uint32_t)c4) * 2u;
                uint2 hi, lo;
                split4(ga[v], hi, lo);
                *(uint2*)(dstS + off) = hi;
                *(uint2*)(dstS + 10240 + off) = lo;
                split4(gb[v], hi, lo);
                *(uint2*)(dstS + 20480 + off) = hi;
                *(uint2*)(dstS + 30720 + off) = lo;
            }
        }
        __syncthreads();
    }

    const int g = lane >> 2, t = lane & 3;
#pragma unroll
    for (int ma = 0; ma < 4; ma++) {
        int r = m0 + wm * 64 + ma * 16 + g;
#pragma unroll
        for (int na = 0; na < 4; na++) {
            int c = n0 + wn * 32 + na * 8 + 2 * t;
            float2 bb = make_float2(0.f, 0.f);
            if (bias) bb = *(const float2*)(bias + c);
            *(float2*)(C + (size_t)r * ldc + c) =
                make_float2(acc[ma][na][0] + bb.x, acc[ma][na][1] + bb.y);
            *(float2*)(C + (size_t)(r + 8) * ldc + c) =
                make_float2(acc[ma][na][2] + bb.x, acc[ma][na][3] + bb.y);
        }
    }
}

// ===== logits queue tile: 64 (batch, step t) x 128 vocab cols, K=512 =====
// A row b = hist[(b*T + t)*512 + k]  (base hist + t*512, row stride 10240)
// Stage: Ah(5120) Al(5120) Bh(10240) Bl(10240) = 30720; 2 stages.
#define LQ_STAGE 30720u
#define LQ_SMEM  (2 * 30720)

__device__ __forceinline__ void logits_tile_fn(
    int id, const float* __restrict__ W_fc, const float* __restrict__ b_fc,
    float* __restrict__ out, char* sb)
{
    const int t = id / 250;
    const int n0 = (id % 250) * 128;
    const float* Ab = d_hist + t * 512;
    const uint32_t ub = smem_u32(sb);
    const int tid = threadIdx.x, lane = tid & 31, wid = tid >> 5;
    const int wm = wid & 1, wn = wid >> 1;     // warp grid 2(M) x 4(N), tile 32x32
    const int arow = tid >> 2, ac = (tid & 3) << 3;   // 64 A rows, 8 floats/thr
    const int brow = tid >> 1, bc = (tid & 1) << 4;   // 128 B rows, 16 floats/thr
    const uint32_t aLane = (((uint32_t)(lane & 15) * 40u) + ((lane >> 4) * 8u)) * 2u;
    const uint32_t bLane = (((uint32_t)(lane & 7) * 40u) + (((lane >> 3) & 1) * 8u)) * 2u;

    float acc[2][4][4];
#pragma unroll
    for (int i = 0; i < 2; i++)
#pragma unroll
        for (int j = 0; j < 4; j++)
#pragma unroll
            for (int q = 0; q < 4; q++) acc[i][j][q] = 0.f;

    float4 ga0, ga1, gb0, gb1, gb2, gb3;

#define LQ_LOAD(kb)                                                               \
    do {                                                                          \
        const float* ap = Ab + (size_t)arow * 10240 + (kb) + ac;                  \
        ga0 = __ldcg((const float4*)ap); ga1 = __ldcg((const float4*)(ap + 4));   \
        const float* bp = W_fc + (size_t)(n0 + brow) * 512 + (kb) + bc;           \
        gb0 = *(const float4*)bp;       gb1 = *(const float4*)(bp + 4);           \
        gb2 = *(const float4*)(bp + 8); gb3 = *(const float4*)(bp + 12);          \
    } while (0)

#define LQ_STORE(dst)                                                             \
    do {                                                                          \
        uint2 hi, lo;                                                             \
        uint32_t ao = ((uint32_t)arow * 40u + (uint32_t)ac) * 2u;                 \
        split4(ga0, hi, lo);                                                      \
        *(uint2*)((dst) + ao) = hi;      *(uint2*)((dst) + 5120 + ao) = lo;       \
        split4(ga1, hi, lo);                                                      \
        *(uint2*)((dst) + ao + 8) = hi;  *(uint2*)((dst) + 5120 + ao + 8) = lo;   \
        uint32_t bo = ((uint32_t)brow * 40u + (uint32_t)bc) * 2u;                 \
        split4(gb0, hi, lo);                                                      \
        *(uint2*)((dst) + 10240 + bo) = hi;      *(uint2*)((dst) + 20480 + bo) = lo; \
        split4(gb1, hi, lo);                                                      \
        *(uint2*)((dst) + 10240 + bo + 8) = hi;  *(uint2*)((dst) + 20480 + bo + 8) = lo; \
        split4(gb2, hi, lo);                                                      \
        *(uint2*)((dst) + 10240 + bo + 16) = hi; *(uint2*)((dst) + 20480 + bo + 16) = lo; \
        split4(gb3, hi, lo);                                                      \
        *(uint2*)((dst) + 10240 + bo + 24) = hi; *(uint2*)((dst) + 20480 + bo + 24) = lo; \
    } while (0)

    LQ_LOAD(0);
    LQ_STORE(sb);
    __syncthreads();

    for (int ich = 0; ich < 16; ich++) {
        const bool pf = (ich + 1 < 16);
        if (pf) LQ_LOAD((ich + 1) << 5);
        const uint32_t st = ub + (uint32_t)(ich & 1) * LQ_STAGE;
#pragma unroll
        for (int kk = 0; kk < 2; kk++) {
            uint32_t Ah[2][4], Al[2][4], Bh[4][2], Bl[4][2];
#pragma unroll
            for (int ma = 0; ma < 2; ma++) {
                uint32_t ad = st + (uint32_t)(wm * 32 + ma * 16) * 80u + aLane + kk * 32u;
                ldsm4(Ah[ma], ad);
                ldsm4(Al[ma], ad + 5120u);
            }
#pragma unroll
            for (int na = 0; na < 4; na++) {
                uint32_t bd = st + 10240u + (uint32_t)(wn * 32 + na * 8) * 80u + bLane + kk * 32u;
                ldsm2(Bh[na], bd);
                ldsm2(Bl[na], bd + 10240u);
            }
#pragma unroll
            for (int ma = 0; ma < 2; ma++)
#pragma unroll
                for (int na = 0; na < 4; na++) {
                    mma_bf16(acc[ma][na], Ah[ma], Bh[na]);
                    mma_bf16(acc[ma][na], Al[ma], Bh[na]);
                    mma_bf16(acc[ma][na], Ah[ma], Bl[na]);
                }
        }
        if (pf) LQ_STORE(sb + ((ich + 1) & 1) * LQ_STAGE);
        __syncthreads();
    }
#undef LQ_LOAD
#undef LQ_STORE

    const int g = lane >> 2, qt = lane & 3;
#pragma unroll
    for (int ma = 0; ma < 2; ma++) {
        int b = wm * 32 + ma * 16 + g;
#pragma unroll
        for (int na = 0; na < 4; na++) {
            int c = n0 + wn * 32 + na * 8 + 2 * qt;
            float2 bb = *(const float2*)(b_fc + c);
            *(float2*)(out + (size_t)(b * T_ + t) * V_ + c) =
                make_float2(acc[ma][na][0] + bb.x, acc[ma][na][1] + bb.y);
            *(float2*)(out + (size_t)((b + 8) * T_ + t) * V_ + c) =
                make_float2(acc[ma][na][2] + bb.x, acc[ma][na][3] + bb.y);
        }
    }
}

// ==================== persistent recurrence kernel =======================
struct AttnSh {
    float hp[512];
    float ctx[8][512];
    float m[8], s[8];
};
#define RC_STAGE 36864u
#define RC_SMEM  (2 * 36864)

// barrier over 128 worker CTAs only
__device__ __forceinline__ void gbar(unsigned& bar)
{
    bar += NW;
    __threadfence();
    __syncthreads();
    if (threadIdx.x == 0) {
        atomicAdd(&g_cnt, 1u);
        volatile unsigned* pc = &g_cnt;
        while (*pc < bar) { __nanosleep(64); }
    }
    __syncthreads();
}

__device__ __forceinline__ void gemm64_hmma(
    const __nv_bfloat16* __restrict__ Agh, const __nv_bfloat16* __restrict__ Agl, int lda,
    int kbeg, int klen,
    const __nv_bfloat16* __restrict__ Bgh, const __nv_bfloat16* __restrict__ Bgl,
    int ldb, int n0,
    float* __restrict__ Cp, int ldc, char* sb)
{
    const uint32_t ub = smem_u32(sb);
    const int tid = threadIdx.x, lane = tid & 31, wid = tid >> 5;
    const int wm = wid & 1, wn = wid >> 1;
    const int grow = tid >> 2;
    const int gc0 = (tid & 3) << 3;
    const uint32_t aLane = (uint32_t)((lane & 15) * 144 + (lane >> 4) * 16);
    const uint32_t bLane = (uint32_t)((lane & 7) * 144 + ((lane >> 3) & 1) * 16);

    float acc[2][2][4];
#pragma unroll
    for (int i = 0; i < 2; i++)
#pragma unroll
        for (int j = 0; j < 2; j++)
#pragma unroll
            for (int q = 0; q < 4; q++) acc[i][j][q] = 0.f;

    const int nch = klen >> 6;
    uint4 rah0, rah1, ral0, ral1, rbh0, rbh1, rbl0, rbl1;

#define RC_LOAD(kb)                                                              \
    do {                                                                         \
        const __nv_bfloat16* ap = Agh + (size_t)grow * lda + (kb) + gc0;         \
        const __nv_bfloat16* alp = Agl + (size_t)grow * lda + (kb) + gc0;        \
        const __nv_bfloat16* bp = Bgh + (size_t)(n0 + grow) * ldb + (kb) + gc0;  \
        const __nv_bfloat16* blp = Bgl + (size_t)(n0 + grow) * ldb + (kb) + gc0; \
        rah0 = __ldcg((const uint4*)ap);  rah1 = __ldcg((const uint4*)(ap + 32));  \
        ral0 = __ldcg((const uint4*)alp); ral1 = __ldcg((const uint4*)(alp + 32)); \
        rbh0 = *(const uint4*)bp;         rbh1 = *(const uint4*)(bp + 32);       \
        rbl0 = *(const uint4*)blp;        rbl1 = *(const uint4*)(blp + 32);      \
    } while (0)

#define RC_STORE(stg)                                                            \
    do {                                                                         \
        uint32_t so = (stg) + (uint32_t)(grow * 144 + gc0 * 2);                  \
        *(uint4*)(sb + so) = rah0;          *(uint4*)(sb + so + 64) = rah1;      \
        *(uint4*)(sb + 9216 + so) = ral0;   *(uint4*)(sb + 9216 + so + 64) = ral1; \
        *(uint4*)(sb + 18432 + so) = rbh0;  *(uint4*)(sb + 18432 + so + 64) = rbh1; \
        *(uint4*)(sb + 27648 + so) = rbl0;  *(uint4*)(sb + 27648 + so + 64) = rbl1; \
    } while (0)

    RC_LOAD(kbeg);
    RC_STORE(0u);
    __syncthreads();

    for (int ich = 0; ich < nch; ich++) {
        const bool pf = (ich + 1 < nch);
        if (pf) RC_LOAD(kbeg + ((ich + 1) << 6));
        const uint32_t st = (uint32_t)(ich & 1) * RC_STAGE;
#pragma unroll
        for (int kk = 0; kk < 4; kk++) {
            uint32_t Ahf[2][4], Alf[2][4], Bhf[2][2], Blf[2][2];
#pragma unroll
            for (int ma = 0; ma < 2; ma++) {
                uint32_t ro = st + (uint32_t)(wm * 32 + ma * 16) * 144u + aLane + kk * 32u;
                ldsm4(Ahf[ma], ub + ro);
                ldsm4(Alf[ma], ub + 9216u + ro);
            }
#pragma unroll
            for (int na = 0; na < 2; na++) {
                uint32_t co = st + 18432u + (uint32_t)(wn * 16 + na * 8) * 144u + bLane + kk * 32u;
                ldsm2(Bhf[na], ub + co);
                ldsm2(Blf[na], ub + 9216u + co);
            }
#pragma unroll
            for (int ma = 0; ma < 2; ma++)
#pragma unroll
                for (int na = 0; na < 2; na++) {
                    mma_bf16(acc[ma][na], Ahf[ma], Bhf[na]);
                    mma_bf16(acc[ma][na], Alf[ma], Bhf[na]);
                    mma_bf16(acc[ma][na], Ahf[ma], Blf[na]);
                }
        }
        if (pf) RC_STORE((uint32_t)((ich + 1) & 1) * RC_STAGE);
        __syncthreads();
    }
#undef RC_LOAD
#undef RC_STORE

    const int gq = lane >> 2, qt = lane & 3;
#pragma unroll
    for (int ma = 0; ma < 2; ma++) {
        int r = wm * 32 + ma * 16 + gq;
#pragma unroll
        for (int na = 0; na < 2; na++) {
            int c = n0 + wn * 16 + na * 8 + qt * 2;
            *(float2*)(Cp + (size_t)r * ldc + c) =
                make_float2(acc[ma][na][0], acc[ma][na][1]);
            *(float2*)(Cp + (size_t)(r + 8) * ldc + c) =
                make_float2(acc[ma][na][2], acc[ma][na][3]);
        }
    }
}

__device__ __forceinline__ int lowbound(const int* __restrict__ a, int n, int v)
{
    int lo = 0, hi = n;
    while (lo < hi) { int mid = (lo + hi) >> 1; if (a[mid] < v) lo = mid + 1; else hi = mid; }
    return lo;
}

__device__ __forceinline__ void attn_phase(int b, const int* __restrict__ batch_idx,
                                           const float* __restrict__ b_a, AttnSh* s)
{
    const int tid = threadIdx.x, lane = tid & 31, w = tid >> 5;
    for (int j = tid; j < 512; j += 256) {
        float v = b_a[j];
#pragma unroll
        for (int kz = 0; kz < 8; kz++)
            v += __ldcg(d_hppart + kz * B_ * H_ + b * 512 + j);
        s->hp[j] = v;
    }
    __syncthreads();

    float hpreg[16];
#pragma unroll
    for (int i = 0; i < 4; i++) {
        float4 t4 = *(const float4*)&s->hp[lane * 16 + i * 4];
        hpreg[i * 4 + 0] = t4.x; hpreg[i * 4 + 1] = t4.y;
        hpreg[i * 4 + 2] = t4.z; hpreg[i * 4 + 3] = t4.w;
    }

    const int s0 = lowbound(batch_idx, NN_, b);
    const int s1 = lowbound(batch_idx, NN_, b + 1);

    float m = -INFINITY, ssum = 0.f;
    float ctx[16];
#pragma unroll
    for (int i = 0; i < 16; i++) ctx[i] = 0.f;

#pragma unroll 2
    for (int n = s0 + w; n < s1; n += 8) {
        const float4* np = (const float4*)(d_node_proj + (size_t)n * 512 + lane * 16);
        float4 a0 = np[0], a1 = np[1], a2 = np[2], a3 = np[3];
        float v[16] = {a0.x, a0.y, a0.z, a0.w, a1.x, a1.y, a1.z, a1.w,
                       a2.x, a2.y, a2.z, a2.w, a3.x, a3.y, a3.z, a3.w};
        float p = 0.f;
#pragma unroll
        for (int i = 0; i < 16; i++) p = fmaf(v[i], hpreg[i], p);
#pragma unroll
        for (int o = 16; o > 0; o >>= 1) p += __shfl_xor_sync(0xffffffffu, p, o);
        float mn = fmaxf(m, p);
        float scale = expf(m - mn);
        float e = expf(p - mn);
        ssum = ssum * scale + e;
#pragma unroll
        for (int i = 0; i < 16; i++) ctx[i] = ctx[i] * scale + e * v[i];
        m = mn;
    }
#pragma unroll
    for (int i = 0; i < 4; i++)
        *(float4*)&s->ctx[w][lane * 16 + i * 4] =
            make_float4(ctx[i * 4], ctx[i * 4 + 1], ctx[i * 4 + 2], ctx[i * 4 + 3]);
    if (lane == 0) { s->m[w] = m; s->s[w] = ssum; }
    __syncthreads();

    float M = -INFINITY;
#pragma unroll
    for (int ww = 0; ww < 8; ww++) M = fmaxf(M, s->m[ww]);
    if (M == -INFINITY) {
        for (int j = tid; j < 512; j += 256) {
            __nv_bfloat16 hh, hl; split1(0.f, hh, hl);
            d_xah[b * 1024 + j] = hh; d_xal[b * 1024 + j] = hl;
        }
    } else {
        float stot = 0.f;
        float ew[8];
#pragma unroll
        for (int ww = 0; ww < 8; ww++) { ew[ww] = expf(s->m[ww] - M); stot += s->s[ww] * ew[ww]; }
        float inv = 1.f / stot;
        for (int j = tid; j < 512; j += 256) {
            float num = 0.f;
#pragma unroll
            for (int ww = 0; ww < 8; ww++) num = fmaf(s->ctx[ww][j], ew[ww], num);
            float v = num * inv;
            __nv_bfloat16 hh, hl; split1(v, hh, hl);
            d_xah[b * 1024 + j] = hh; d_xal[b * 1024 + j] = hl;
        }
    }
}

__device__ __forceinline__ void cell0_phase(int i, int t)
{
    int b = i >> 9, j = i & 511;
    const float* ep = d_embpart + (size_t)t * B_ * G4 + b * G4 + j;
    float g[4];
#pragma unroll
    for (int q = 0; q < 4; q++) {
        float v = ep[q * 512];
#pragma unroll
        for (int kz = 0; kz < 4; kz++)
            v += __ldcg(d_gpart0 + kz * B_ * G4 + b * G4 + q * 512 + j);
        g[q] = v;
    }
    float c = sigf(g[1]) * d_c0[i] + sigf(g[0]) * tanhf(g[2]);
    float h = sigf(g[3]) * tanhf(c);
    d_c0[i] = c;
    __nv_bfloat16 hh, hl; split1(h, hh, hl);
    d_xah[b * 1024 + 512 + j] = hh; d_xal[b * 1024 + 512 + j] = hl;
    d_xbh[b * 1024 + j] = hh;       d_xbl[b * 1024 + j] = hl;
}

__device__ __forceinline__ void cell1_phase(int i, int t)
{
    int b = i >> 9, j = i & 511;
    float g[4];
#pragma unroll
    for (int q = 0; q < 4; q++) {
        float v = d_bs1[q * 512 + j];
#pragma unroll
        for (int kz = 0; kz < 4; kz++)
            v += __ldcg(d_gpart1 + kz * B_ * G4 + b * G4 + q * 512 + j);
        g[q] = v;
    }
    float c = sigf(g[1]) * d_c1[i] + sigf(g[0]) * tanhf(g[2]);
    float h = sigf(g[3]) * tanhf(c);
    d_c1[i] = c;
    __nv_bfloat16 hh, hl; split1(h, hh, hl);
    d_xbh[b * 1024 + 512 + j] = hh; d_xbl[b * 1024 + 512 + j] = hl;
    d_hist[((size_t)b * T_ + t) * H_ + j] = h;
}

__global__ __launch_bounds__(256) void recur_kernel(
    const int* __restrict__ batch_idx, const float* __restrict__ b_a,
    const float* __restrict__ W_fc, const float* __restrict__ b_fc,
    float* __restrict__ out)
{
    extern __shared__ __align__(16) char dsm[];
    __shared__ int sh_id;
    const int blk = blockIdx.x;
    const int tid = threadIdx.x;

    if (blk < NW) {
        // ----- worker: R7-exact 6-phase recurrence, barriers over 128 -----
        unsigned bar = 0;
        for (int t = 0; t < T_; t++) {
            if (blk < 64) {
                int n0 = (blk & 7) * 64, kz = blk >> 3;
                gemm64_hmma(d_xbh + 512, d_xbl + 512, 1024, kz * 64, 64,
                            d_Wah, d_Wal, 512, n0,
                            d_hppart + kz * B_ * H_, 512, dsm);
            }
            gbar(bar);
            if (blk < 64) attn_phase(blk, batch_idx, b_a, (AttnSh*)dsm);
            gbar(bar);
            {
                int n0 = (blk & 31) * 64, kz = blk >> 5;
                gemm64_hmma(d_xah, d_xal, 1024, kz * 256, 256,
                            d_W0h, d_W0l, 1024, n0,
                            d_gpart0 + kz * B_ * G4, G4, dsm);
            }
            gbar(bar);
            cell0_phase(blk * 256 + tid, t);
            gbar(bar);
            {
                int n0 = (blk & 31) * 64, kz = blk >> 5;
                gemm64_hmma(d_xbh, d_xbl, 1024, kz * 256, 256,
                            d_W1h, d_W1l, 1024, n0,
                            d_gpart1 + kz * B_ * G4, G4, dsm);
            }
            gbar(bar);
            cell1_phase(blk * 256 + tid, t);
            gbar(bar);
        }
    } else {
        // ----- consumer: overlap logits tiles on otherwise-idle SMs -----
        for (;;) {
            if (tid == 0) {
                int id = -1;
                if (ldvol(&g_cnt) < (unsigned)(6 * T_ * NW)) {   // recur not done
                    id = atomicAdd(&d_qhead, 1);
                    if (id < NQT) {
                        unsigned need = (unsigned)(6 * (id / 250 + 1) * NW);
                        while (ldvol(&g_cnt) < need) { __nanosleep(128); }
                    }
                }
                sh_id = id;
            }
            __syncthreads();
            int id = sh_id;
            __syncthreads();
            if (id < 0 || id >= NQT) break;
            logits_tile_fn(id, W_fc, b_fc, out, dsm);
        }
    }
}

// ---- drain kernel: remaining queue tiles after the recurrence -----------
__global__ void __launch_bounds__(256, 1) logits_q(
    const float* __restrict__ W_fc, const float* __restrict__ b_fc,
    float* __restrict__ out)
{
    extern __shared__ __align__(16) char dsm[];
    __shared__ int sh_id;
    for (;;) {
        if (threadIdx.x == 0) sh_id = atomicAdd(&d_qhead, 1);
        __syncthreads();
        int id = sh_id;
        __syncthreads();
        if (id >= NQT) return;
        logits_tile_fn(id, W_fc, b_fc, out, dsm);
    }
}

// ---------------- one-time prep ------------------------------------------
__global__ void prep_kernel(
    const float* __restrict__ gf,
    const float* __restrict__ W_a,
    const float* __restrict__ W_ih0, const float* __restrict__ W_hh0,
    const float* __restrict__ b_ih0, const float* __restrict__ b_hh0,
    const float* __restrict__ W_ih1, const float* __restrict__ W_hh1,
    const float* __restrict__ b_ih1, const float* __restrict__ b_hh1,
    const int* __restrict__ captions)
{
    int i = blockIdx.x * blockDim.x + threadIdx.x;
    if (i < G4 * 1024) {
        int n = i >> 10, k = i & 1023;
        float w0 = (k < 512) ? W_ih0[n * 1024 + 512 + k] : W_hh0[n * 512 + (k - 512)];
        float w1 = (k < 512) ? W_ih1[n * 512 + k] : W_hh1[n * 512 + (k - 512)];
        __nv_bfloat16 h, l;
        split1(w0, h, l); d_W0h[i] = h; d_W0l[i] = l;
        split1(w1, h, l); d_W1h[i] = h; d_W1l[i] = l;
    }
    if (i < H_ * H_) {
        __nv_bfloat16 h, l;
        split1(W_a[i], h, l); d_Wah[i] = h; d_Wal[i] = l;
    }
    if (i < G4) { d_bs0[i] = b_ih0[i] + b_hh0[i]; d_bs1[i] = b_ih1[i] + b_hh1[i]; }
    if (i < T_ * B_) { int t = i / 64, b = i % 64; d_gidx[i] = captions[b * T_ + t]; }
    if (i < B_ * H_) {
        int b = i >> 9, j = i & 511;
        __nv_bfloat16 h, l;
        split1(gf[i], h, l);
        d_xah[b * 1024 + 512 + j] = h; d_xal[b * 1024 + 512 + j] = l;  // h0
        d_xbh[b * 1024 + 512 + j] = h; d_xbl[b * 1024 + 512 + j] = l;  // h1
        d_c0[i] = 0.f;
        d_c1[i] = 0.f;
    }
    if (i == 0) { g_cnt = 0u; d_qhead = 0; }
}

// ---------------- launch --------------------------------------------------
extern "C" void kernel_launch(void* const* d_in, const int* in_sizes, int n_in,
                              void* d_out, int out_size)
{
    const float* gf     = (const float*)d_in[0];
    const float* nf     = (const float*)d_in[1];
    const float* emb    = (const float*)d_in[2];
    const float* W_a    = (const float*)d_in[3];
    const float* b_a    = (const float*)d_in[4];
    const float* W_c    = (const float*)d_in[5];
    const float* b_c    = (const float*)d_in[6];
    const float* W_ih0  = (const float*)d_in[7];
    const float* W_hh0  = (const float*)d_in[8];
    const float* b_ih0  = (const float*)d_in[9];
    const float* b_hh0  = (const float*)d_in[10];
    const float* W_ih1  = (const float*)d_in[11];
    const float* W_hh1  = (const float*)d_in[12];
    const float* b_ih1  = (const float*)d_in[13];
    const float* b_hh1  = (const float*)d_in[14];
    const float* W_fc   = (const float*)d_in[15];
    const float* b_fc   = (const float*)d_in[16];
    const int* batch_idx = (const int*)d_in[17];
    const int* captions  = (const int*)d_in[18];
    float* out = (float*)d_out;

    float *node_proj, *embpart, *bs0;
    int* gidx;
    cudaGetSymbolAddress((void**)&node_proj, d_node_proj);
    cudaGetSymbolAddress((void**)&embpart,   d_embpart);
    cudaGetSymbolAddress((void**)&bs0,       d_bs0);
    cudaGetSymbolAddress((void**)&gidx,      d_gidx);

    cudaFuncSetAttribute(tgemm, cudaFuncAttributeMaxDynamicSharedMemorySize, TG_SMEM);
    cudaFuncSetAttribute(recur_kernel, cudaFuncAttributeMaxDynamicSharedMemorySize, RC_SMEM);
    cudaFuncSetAttribute(logits_q, cudaFuncAttributeMaxDynamicSharedMemorySize, LQ_SMEM);

    // one-time prep: weight splits, bias sums, gather indices, state init
    prep_kernel<<<8192, 256>>>(gf, W_a, W_ih0, W_hh0, b_ih0, b_hh0,
                               W_ih1, W_hh1, b_ih1, b_hh1, captions);

    // node_proj = node_features @ W_c^T + b_c         [8192, 512]
    tgemm<<<dim3(NN_ / 128, H_ / 128), 256, TG_SMEM>>>(
        nf, H_, W_c, H_, node_proj, H_, b_c, H_, nullptr);

    // embpart = emb[captions] @ W_ih0[:, :512]^T + (b_ih0+b_hh0)   [1280, 2048]
    tgemm<<<dim3(T_ * B_ / 128, G4 / 128), 256, TG_SMEM>>>(
        emb, E_, W_ih0, 1024, embpart, G4, bs0, E_, gidx);

    // recurrence (128 worker CTAs) + overlapped logits consumers (20 CTAs)
    recur_kernel<<<NB, 256, RC_SMEM>>>(batch_idx, b_a, W_fc, b_fc, out);

    // drain remaining logits tiles with the full chip
    logits_q<<<NB, 256, LQ_SMEM>>>(W_fc, b_fc, out);
}

// round 16
// speedup vs baseline: 1.2000x; 1.2000x over previous
#include <cuda_runtime.h>
#include <cuda_bf16.h>
#include <math.h>
#include <stdint.h>

#define B_  64
#define T_  20
#define H_  512
#define E_  512
#define V_  32000
#define NN_ 8192
#define G4  2048   // 4*H
#define NB  148    // total grid
#define NW  128    // worker CTAs participating in barriers
#define NQT 2500   // logits tiles: 10 t-pairs x 250 col-tiles of 128

// ---------------- static scratch (no allocations allowed) ----------------
__device__ float d_node_proj[NN_ * H_];
__device__ float d_embpart[T_ * B_ * G4];
__device__ float d_hist[B_ * T_ * H_];
__device__ float d_c0[B_ * H_];
__device__ float d_c1[B_ * H_];
__device__ float d_bs0[G4];
__device__ float d_bs1[G4];
__device__ int   d_gidx[T_ * B_];

__device__ __nv_bfloat16 d_Wah[H_ * H_], d_Wal[H_ * H_];
__device__ __nv_bfloat16 d_W0h[G4 * 1024], d_W0l[G4 * 1024];
__device__ __nv_bfloat16 d_W1h[G4 * 1024], d_W1l[G4 * 1024];
__device__ __nv_bfloat16 d_xah[B_ * 1024], d_xal[B_ * 1024];
__device__ __nv_bfloat16 d_xbh[B_ * 1024], d_xbl[B_ * 1024];

__device__ float d_hppart[8 * B_ * H_];
__device__ float d_gpart0[4 * B_ * G4];
__device__ float d_gpart1[4 * B_ * G4];
__device__ unsigned g_cnt;    // barrier arrivals (128 workers x 6/step)
__device__ int d_qhead;       // logits tile queue head

// ===================== helpers =====================
__device__ __forceinline__ uint32_t smem_u32(const void* p) {
    uint32_t a;
    asm("{ .reg .u64 t; cvta.to.shared.u64 t, %1; cvt.u32.u64 %0, t; }"
        : "=r"(a) : "l"(p));
    return a;
}
__device__ __forceinline__ void ldsm4(uint32_t* r, uint32_t addr) {
    asm volatile("ldmatrix.sync.aligned.m8n8.x4.shared.b16 {%0,%1,%2,%3}, [%4];"
                 : "=r"(r[0]), "=r"(r[1]), "=r"(r[2]), "=r"(r[3]) : "r"(addr));
}
__device__ __forceinline__ void ldsm2(uint32_t* r, uint32_t addr) {
    asm volatile("ldmatrix.sync.aligned.m8n8.x2.shared.b16 {%0,%1}, [%2];"
                 : "=r"(r[0]), "=r"(r[1]) : "r"(addr));
}
__device__ __forceinline__ void mma_bf16(float* d, const uint32_t* a, const uint32_t* b) {
    asm volatile(
        "mma.sync.aligned.m16n8k16.row.col.f32.bf16.bf16.f32 "
        "{%0,%1,%2,%3}, {%4,%5,%6,%7}, {%8,%9}, {%0,%1,%2,%3};"
        : "+f"(d[0]), "+f"(d[1]), "+f"(d[2]), "+f"(d[3])
        : "r"(a[0]), "r"(a[1]), "r"(a[2]), "r"(a[3]), "r"(b[0]), "r"(b[1]));
}
__device__ __forceinline__ unsigned ldvol(const unsigned* p) {
    unsigned v;
    asm volatile("ld.global.cg.u32 %0, [%1];" : "=r"(v) : "l"(p) : "memory");
    return v;
}
__device__ __forceinline__ void split1(float v, __nv_bfloat16& h, __nv_bfloat16& l) {
    h = __float2bfloat16(v);
    l = __float2bfloat16(v - __bfloat162float(h));
}
__device__ __forceinline__ void split4(float4 a, uint2& hi, uint2& lo) {
    __nv_bfloat16 h0, h1, h2, h3, l0, l1, l2, l3;
    split1(a.x, h0, l0); split1(a.y, h1, l1);
    split1(a.z, h2, l2); split1(a.w, h3, l3);
    __nv_bfloat162 ph = __nv_bfloat162(h0, h1), qh = __nv_bfloat162(h2, h3);
    __nv_bfloat162 pl = __nv_bfloat162(l0, l1), ql = __nv_bfloat162(l2, l3);
    hi = make_uint2(*(uint32_t*)&ph, *(uint32_t*)&qh);
    lo = make_uint2(*(uint32_t*)&pl, *(uint32_t*)&ql);
}
__device__ __forceinline__ float sigf(float x) { return 1.f / (1.f + expf(-x)); }

// ========== big split-bf16 HMMA GEMM (validated R3/R4) ===================
#define TG_STAGE 40960
#define TG_SMEM  (2 * TG_STAGE)

__global__ void __launch_bounds__(256, 1) tgemm(
    const float* __restrict__ A, int lda,
    const float* __restrict__ Bw, int ldb,
    float* __restrict__ C, int ldc,
    const float* __restrict__ bias,
    int K, const int* __restrict__ gidx)
{
    extern __shared__ char sm[];
    const uint32_t sbase = smem_u32(sm);
    const int tid = threadIdx.x;
    const int lane = tid & 31, wid = tid >> 5;
    const int wm = wid & 1, wn = wid >> 1;
    const int m0 = blockIdx.x * 128, n0 = blockIdx.y * 128;
    const int lrow = tid >> 3;
    const int c4 = (tid & 7) << 2;
    const uint32_t aLane = (((uint32_t)(lane & 15) * 40u) + ((lane >> 4) * 8u)) * 2u;
    const uint32_t bLane = (((uint32_t)(lane & 7) * 40u) + (((lane >> 3) & 1) * 8u)) * 2u;

    float acc[4][4][4];
#pragma unroll
    for (int i = 0; i < 4; i++)
#pragma unroll
        for (int j = 0; j < 4; j++)
#pragma unroll
            for (int q = 0; q < 4; q++) acc[i][j][q] = 0.f;

    const int nch = K >> 5;
    float4 ga[4], gb[4];
#pragma unroll
    for (int v = 0; v < 4; v++) {
        int row = lrow + v * 32;
        int gr = gidx ? gidx[m0 + row] : (m0 + row);
        ga[v] = *(const float4*)(A + (size_t)gr * lda + c4);
        gb[v] = *(const float4*)(Bw + (size_t)(n0 + row) * ldb + c4);
    }
#pragma unroll
    for (int v = 0; v < 4; v++) {
        int row = lrow + v * 32;
        uint32_t off = ((uint32_t)row * 40u + (uint32_t)c4) * 2u;
        uint2 hi, lo;
        split4(ga[v], hi, lo);
        *(uint2*)(sm + off) = hi;
        *(uint2*)(sm + 10240 + off) = lo;
        split4(gb[v], hi, lo);
        *(uint2*)(sm + 20480 + off) = hi;
        *(uint2*)(sm + 30720 + off) = lo;
    }
    __syncthreads();

    for (int ich = 0; ich < nch; ich++) {
        const bool pf = (ich + 1 < nch);
        if (pf) {
            const int kb = (ich + 1) << 5;
#pragma unroll
            for (int v = 0; v < 4; v++) {
                int row = lrow + v * 32;
                int gr = gidx ? gidx[m0 + row] : (m0 + row);
                ga[v] = *(const float4*)(A + (size_t)gr * lda + kb + c4);
                gb[v] = *(const float4*)(Bw + (size_t)(n0 + row) * ldb + kb + c4);
            }
        }
        const uint32_t st = sbase + (uint32_t)(ich & 1) * TG_STAGE;
#pragma unroll
        for (int kk = 0; kk < 2; kk++) {
            uint32_t Ah[4][4], Al[4][4], Bh[4][2], Bl[4][2];
#pragma unroll
            for (int ma = 0; ma < 4; ma++) {
                uint32_t ad = st + (uint32_t)(wm * 64 + ma * 16) * 80u + aLane + kk * 32u;
                ldsm4(Ah[ma], ad);
                ldsm4(Al[ma], ad + 10240u);
            }
#pragma unroll
            for (int na = 0; na < 4; na++) {
                uint32_t bd = st + 20480u + (uint32_t)(wn * 32 + na * 8) * 80u + bLane + kk * 32u;
                ldsm2(Bh[na], bd);
                ldsm2(Bl[na], bd + 10240u);
            }
#pragma unroll
            for (int ma = 0; ma < 4; ma++)
#pragma unroll
                for (int na = 0; na < 4; na++) {
                    mma_bf16(acc[ma][na], Ah[ma], Bh[na]);
                    mma_bf16(acc[ma][na], Al[ma], Bh[na]);
                    mma_bf16(acc[ma][na], Ah[ma], Bl[na]);
                }
        }
        if (pf) {
            char* dstS = sm + ((ich + 1) & 1) * TG_STAGE;
#pragma unroll
            for (int v = 0; v < 4; v++) {
                int row = lrow + v * 32;
                uint32_t off = ((uint32_t)row * 40u + (uint32_t)c4) * 2u;
                uint2 hi, lo;
                split4(ga[v], hi, lo);
                *(uint2*)(dstS + off) = hi;
                *(uint2*)(dstS + 10240 + off) = lo;
                split4(gb[v], hi, lo);
                *(uint2*)(dstS + 20480 + off) = hi;
                *(uint2*)(dstS + 30720 + off) = lo;
            }
        }
        __syncthreads();
    }

    const int g = lane >> 2, t = lane & 3;
#pragma unroll
    for (int ma = 0; ma < 4; ma++) {
        int r = m0 + wm * 64 + ma * 16 + g;
#pragma unroll
        for (int na = 0; na < 4; na++) {
            int c = n0 + wn * 32 + na * 8 + 2 * t;
            float2 bb = make_float2(0.f, 0.f);
            if (bias) bb = *(const float2*)(bias + c);
            *(float2*)(C + (size_t)r * ldc + c) =
                make_float2(acc[ma][na][0] + bb.x, acc[ma][na][1] + bb.y);
            *(float2*)(C + (size_t)(r + 8) * ldc + c) =
                make_float2(acc[ma][na][2] + bb.x, acc[ma][na][3] + bb.y);
        }
    }
}

// ===== logits queue tile: PROVEN 128x128 tgemm body, rows = (b, t-pair) ==
// tile id -> tp = id/250 (steps 2tp,2tp+1), n0 = (id%250)*128.
// local row r in 0..127 -> hist/out row gr = (r>>1)*T + 2tp + (r&1). K=512.
__device__ void logits_tile128(
    int id, const float* __restrict__ W_fc, const float* __restrict__ b_fc,
    float* __restrict__ out, char* sm)
{
    const uint32_t sbase = smem_u32(sm);
    const int tid = threadIdx.x;
    const int lane = tid & 31, wid = tid >> 5;
    const int wm = wid & 1, wn = wid >> 1;
    const int tp2 = (id / 250) * 2;
    const int n0 = (id % 250) * 128;
    const int lrow = tid >> 3;
    const int c4 = (tid & 7) << 2;
    const uint32_t aLane = (((uint32_t)(lane & 15) * 40u) + ((lane >> 4) * 8u)) * 2u;
    const uint32_t bLane = (((uint32_t)(lane & 7) * 40u) + (((lane >> 3) & 1) * 8u)) * 2u;

#define QROW(r) (((r) >> 1) * T_ + tp2 + ((r) & 1))

    float acc[4][4][4];
#pragma unroll
    for (int i = 0; i < 4; i++)
#pragma unroll
        for (int j = 0; j < 4; j++)
#pragma unroll
            for (int q = 0; q < 4; q++) acc[i][j][q] = 0.f;

    float4 ga[4], gb[4];
#pragma unroll
    for (int v = 0; v < 4; v++) {
        int row = lrow + v * 32;
        ga[v] = __ldcg((const float4*)(d_hist + (size_t)QROW(row) * 512 + c4));
        gb[v] = *(const float4*)(W_fc + (size_t)(n0 + row) * 512 + c4);
    }
#pragma unroll
    for (int v = 0; v < 4; v++) {
        int row = lrow + v * 32;
        uint32_t off = ((uint32_t)row * 40u + (uint32_t)c4) * 2u;
        uint2 hi, lo;
        split4(ga[v], hi, lo);
        *(uint2*)(sm + off) = hi;
        *(uint2*)(sm + 10240 + off) = lo;
        split4(gb[v], hi, lo);
        *(uint2*)(sm + 20480 + off) = hi;
        *(uint2*)(sm + 30720 + off) = lo;
    }
    __syncthreads();

    for (int ich = 0; ich < 16; ich++) {
        const bool pf = (ich + 1 < 16);
        if (pf) {
            const int kb = (ich + 1) << 5;
#pragma unroll
            for (int v = 0; v < 4; v++) {
                int row = lrow + v * 32;
                ga[v] = __ldcg((const float4*)(d_hist + (size_t)QROW(row) * 512 + kb + c4));
                gb[v] = *(const float4*)(W_fc + (size_t)(n0 + row) * 512 + kb + c4);
            }
        }
        const uint32_t st = sbase + (uint32_t)(ich & 1) * TG_STAGE;
#pragma unroll
        for (int kk = 0; kk < 2; kk++) {
            uint32_t Ah[4][4], Al[4][4], Bh[4][2], Bl[4][2];
#pragma unroll
            for (int ma = 0; ma < 4; ma++) {
                uint32_t ad = st + (uint32_t)(wm * 64 + ma * 16) * 80u + aLane + kk * 32u;
                ldsm4(Ah[ma], ad);
                ldsm4(Al[ma], ad + 10240u);
            }
#pragma unroll
            for (int na = 0; na < 4; na++) {
                uint32_t bd = st + 20480u + (uint32_t)(wn * 32 + na * 8) * 80u + bLane + kk * 32u;
                ldsm2(Bh[na], bd);
                ldsm2(Bl[na], bd + 10240u);
            }
#pragma unroll
            for (int ma = 0; ma < 4; ma++)
#pragma unroll
                for (int na = 0; na < 4; na++) {
                    mma_bf16(acc[ma][na], Ah[ma], Bh[na]);
                    mma_bf16(acc[ma][na], Al[ma], Bh[na]);
                    mma_bf16(acc[ma][na], Ah[ma], Bl[na]);
                }
        }
        if (pf) {
            char* dstS = sm + ((ich + 1) & 1) * TG_STAGE;
#pragma unroll
            for (int v = 0; v < 4; v++) {
                int row = lrow + v * 32;
                uint32_t off = ((uint32_t)row * 40u + (uint32_t)c4) * 2u;
                uint2 hi, lo;
                split4(ga[v], hi, lo);
                *(uint2*)(dstS + off) = hi;
                *(uint2*)(dstS + 10240 + off) = lo;
                split4(gb[v], hi, lo);
                *(uint2*)(dstS + 20480 + off) = hi;
                *(uint2*)(dstS + 30720 + off) = lo;
            }
        }
        __syncthreads();
    }

    const int g = lane >> 2, qt = lane & 3;
#pragma unroll
    for (int ma = 0; ma < 4; ma++) {
        int rl = wm * 64 + ma * 16 + g;
#pragma unroll
        for (int na = 0; na < 4; na++) {
            int c = n0 + wn * 32 + na * 8 + 2 * qt;
            float2 bb = *(const float2*)(b_fc + c);
            *(float2*)(out + (size_t)QROW(rl) * V_ + c) =
                make_float2(acc[ma][na][0] + bb.x, acc[ma][na][1] + bb.y);
            *(float2*)(out + (size_t)QROW(rl + 8) * V_ + c) =
                make_float2(acc[ma][na][2] + bb.x, acc[ma][na][3] + bb.y);
        }
    }
#undef QROW
}

// ==================== persistent recurrence kernel =======================
struct AttnSh {
    float hp[512];
    float ctx[8][512];
    float m[8], s[8];
};
#define RC_STAGE 36864u
#define RC_SMEM  TG_SMEM   // max(recur stages 73728, logits tile 81920)

// barrier over 128 worker CTAs only
__device__ __forceinline__ void gbar(unsigned& bar)
{
    bar += NW;
    __threadfence();
    __syncthreads();
    if (threadIdx.x == 0) {
        atomicAdd(&g_cnt, 1u);
        volatile unsigned* pc = &g_cnt;
        while (*pc < bar) { __nanosleep(64); }
    }
    __syncthreads();
}

__device__ __forceinline__ void gemm64_hmma(
    const __nv_bfloat16* __restrict__ Agh, const __nv_bfloat16* __restrict__ Agl, int lda,
    int kbeg, int klen,
    const __nv_bfloat16* __restrict__ Bgh, const __nv_bfloat16* __restrict__ Bgl,
    int ldb, int n0,
    float* __restrict__ Cp, int ldc, char* sb)
{
    const uint32_t ub = smem_u32(sb);
    const int tid = threadIdx.x, lane = tid & 31, wid = tid >> 5;
    const int wm = wid & 1, wn = wid >> 1;
    const int grow = tid >> 2;
    const int gc0 = (tid & 3) << 3;
    const uint32_t aLane = (uint32_t)((lane & 15) * 144 + (lane >> 4) * 16);
    const uint32_t bLane = (uint32_t)((lane & 7) * 144 + ((lane >> 3) & 1) * 16);

    float acc[2][2][4];
#pragma unroll
    for (int i = 0; i < 2; i++)
#pragma unroll
        for (int j = 0; j < 2; j++)
#pragma unroll
            for (int q = 0; q < 4; q++) acc[i][j][q] = 0.f;

    const int nch = klen >> 6;
    uint4 rah0, rah1, ral0, ral1, rbh0, rbh1, rbl0, rbl1;

#define RC_LOAD(kb)                                                              \
    do {                                                                         \
        const __nv_bfloat16* ap = Agh + (size_t)grow * lda + (kb) + gc0;         \
        const __nv_bfloat16* alp = Agl + (size_t)grow * lda + (kb) + gc0;        \
        const __nv_bfloat16* bp = Bgh + (size_t)(n0 + grow) * ldb + (kb) + gc0;  \
        const __nv_bfloat16* blp = Bgl + (size_t)(n0 + grow) * ldb + (kb) + gc0; \
        rah0 = __ldcg((const uint4*)ap);  rah1 = __ldcg((const uint4*)(ap + 32));  \
        ral0 = __ldcg((const uint4*)alp); ral1 = __ldcg((const uint4*)(alp + 32)); \
        rbh0 = *(const uint4*)bp;         rbh1 = *(const uint4*)(bp + 32);       \
        rbl0 = *(const uint4*)blp;        rbl1 = *(const uint4*)(blp + 32);      \
    } while (0)

#define RC_STORE(stg)                                                            \
    do {                                                                         \
        uint32_t so = (stg) + (uint32_t)(grow * 144 + gc0 * 2);                  \
        *(uint4*)(sb + so) = rah0;          *(uint4*)(sb + so + 64) = rah1;      \
        *(uint4*)(sb + 9216 + so) = ral0;   *(uint4*)(sb + 9216 + so + 64) = ral1; \
        *(uint4*)(sb + 18432 + so) = rbh0;  *(uint4*)(sb + 18432 + so + 64) = rbh1; \
        *(uint4*)(sb + 27648 + so) = rbl0;  *(uint4*)(sb + 27648 + so + 64) = rbl1; \
    } while (0)

    RC_LOAD(kbeg);
    RC_STORE(0u);
    __syncthreads();

    for (int ich = 0; ich < nch; ich++) {
        const bool pf = (ich + 1 < nch);
        if (pf) RC_LOAD(kbeg + ((ich + 1) << 6));
        const uint32_t st = (uint32_t)(ich & 1) * RC_STAGE;
#pragma unroll
        for (int kk = 0; kk < 4; kk++) {
            uint32_t Ahf[2][4], Alf[2][4], Bhf[2][2], Blf[2][2];
#pragma unroll
            for (int ma = 0; ma < 2; ma++) {
                uint32_t ro = st + (uint32_t)(wm * 32 + ma * 16) * 144u + aLane + kk * 32u;
                ldsm4(Ahf[ma], ub + ro);
                ldsm4(Alf[ma], ub + 9216u + ro);
            }
#pragma unroll
            for (int na = 0; na < 2; na++) {
                uint32_t co = st + 18432u + (uint32_t)(wn * 16 + na * 8) * 144u + bLane + kk * 32u;
                ldsm2(Bhf[na], ub + co);
                ldsm2(Blf[na], ub + 9216u + co);
            }
#pragma unroll
            for (int ma = 0; ma < 2; ma++)
#pragma unroll
                for (int na = 0; na < 2; na++) {
                    mma_bf16(acc[ma][na], Ahf[ma], Bhf[na]);
                    mma_bf16(acc[ma][na], Alf[ma], Bhf[na]);
                    mma_bf16(acc[ma][na], Ahf[ma], Blf[na]);
                }
        }
        if (pf) RC_STORE((uint32_t)((ich + 1) & 1) * RC_STAGE);
        __syncthreads();
    }
#undef RC_LOAD
#undef RC_STORE

    const int gq = lane >> 2, qt = lane & 3;
#pragma unroll
    for (int ma = 0; ma < 2; ma++) {
        int r = wm * 32 + ma * 16 + gq;
#pragma unroll
        for (int na = 0; na < 2; na++) {
            int c = n0 + wn * 16 + na * 8 + qt * 2;
            *(float2*)(Cp + (size_t)r * ldc + c) =
                make_float2(acc[ma][na][0], acc[ma][na][1]);
            *(float2*)(Cp + (size_t)(r + 8) * ldc + c) =
                make_float2(acc[ma][na][2], acc[ma][na][3]);
        }
    }
}

__device__ __forceinline__ int lowbound(const int* __restrict__ a, int n, int v)
{
    int lo = 0, hi = n;
    while (lo < hi) { int mid = (lo + hi) >> 1; if (a[mid] < v) lo = mid + 1; else hi = mid; }
    return lo;
}

__device__ __forceinline__ void attn_phase(int b, const int* __restrict__ batch_idx,
                                           const float* __restrict__ b_a, AttnSh* s)
{
    const int tid = threadIdx.x, lane = tid & 31, w = tid >> 5;
    for (int j = tid; j < 512; j += 256) {
        float v = b_a[j];
#pragma unroll
        for (int kz = 0; kz < 8; kz++)
            v += __ldcg(d_hppart + kz * B_ * H_ + b * 512 + j);
        s->hp[j] = v;
    }
    __syncthreads();

    float hpreg[16];
#pragma unroll
    for (int i = 0; i < 4; i++) {
        float4 t4 = *(const float4*)&s->hp[lane * 16 + i * 4];
        hpreg[i * 4 + 0] = t4.x; hpreg[i * 4 + 1] = t4.y;
        hpreg[i * 4 + 2] = t4.z; hpreg[i * 4 + 3] = t4.w;
    }

    const int s0 = lowbound(batch_idx, NN_, b);
    const int s1 = lowbound(batch_idx, NN_, b + 1);

    float m = -INFINITY, ssum = 0.f;
    float ctx[16];
#pragma unroll
    for (int i = 0; i < 16; i++) ctx[i] = 0.f;

#pragma unroll 2
    for (int n = s0 + w; n < s1; n += 8) {
        const float4* np = (const float4*)(d_node_proj + (size_t)n * 512 + lane * 16);
        float4 a0 = np[0], a1 = np[1], a2 = np[2], a3 = np[3];
        float v[16] = {a0.x, a0.y, a0.z, a0.w, a1.x, a1.y, a1.z, a1.w,
                       a2.x, a2.y, a2.z, a2.w, a3.x, a3.y, a3.z, a3.w};
        float p = 0.f;
#pragma unroll
        for (int i = 0; i < 16; i++) p = fmaf(v[i], hpreg[i], p);
#pragma unroll
        for (int o = 16; o > 0; o >>= 1) p += __shfl_xor_sync(0xffffffffu, p, o);
        float mn = fmaxf(m, p);
        float scale = expf(m - mn);
        float e = expf(p - mn);
        ssum = ssum * scale + e;
#pragma unroll
        for (int i = 0; i < 16; i++) ctx[i] = ctx[i] * scale + e * v[i];
        m = mn;
    }
#pragma unroll
    for (int i = 0; i < 4; i++)
        *(float4*)&s->ctx[w][lane * 16 + i * 4] =
            make_float4(ctx[i * 4], ctx[i * 4 + 1], ctx[i * 4 + 2], ctx[i * 4 + 3]);
    if (lane == 0) { s->m[w] = m; s->s[w] = ssum; }
    __syncthreads();

    float M = -INFINITY;
#pragma unroll
    for (int ww = 0; ww < 8; ww++) M = fmaxf(M, s->m[ww]);
    if (M == -INFINITY) {
        for (int j = tid; j < 512; j += 256) {
            __nv_bfloat16 hh, hl; split1(0.f, hh, hl);
            d_xah[b * 1024 + j] = hh; d_xal[b * 1024 + j] = hl;
        }
    } else {
        float stot = 0.f;
        float ew[8];
#pragma unroll
        for (int ww = 0; ww < 8; ww++) { ew[ww] = expf(s->m[ww] - M); stot += s->s[ww] * ew[ww]; }
        float inv = 1.f / stot;
        for (int j = tid; j < 512; j += 256) {
            float num = 0.f;
#pragma unroll
            for (int ww = 0; ww < 8; ww++) num = fmaf(s->ctx[ww][j], ew[ww], num);
            float v = num * inv;
            __nv_bfloat16 hh, hl; split1(v, hh, hl);
            d_xah[b * 1024 + j] = hh; d_xal[b * 1024 + j] = hl;
        }
    }
}

__device__ __forceinline__ void cell0_phase(int i, int t)
{
    int b = i >> 9, j = i & 511;
    const float* ep = d_embpart + (size_t)t * B_ * G4 + b * G4 + j;
    float g[4];
#pragma unroll
    for (int q = 0; q < 4; q++) {
        float v = ep[q * 512];
#pragma unroll
        for (int kz = 0; kz < 4; kz++)
            v += __ldcg(d_gpart0 + kz * B_ * G4 + b * G4 + q * 512 + j);
        g[q] = v;
    }
    float c = sigf(g[1]) * d_c0[i] + sigf(g[0]) * tanhf(g[2]);
    float h = sigf(g[3]) * tanhf(c);
    d_c0[i] = c;
    __nv_bfloat16 hh, hl; split1(h, hh, hl);
    d_xah[b * 1024 + 512 + j] = hh; d_xal[b * 1024 + 512 + j] = hl;
    d_xbh[b * 1024 + j] = hh;       d_xbl[b * 1024 + j] = hl;
}

__device__ __forceinline__ void cell1_phase(int i, int t)
{
    int b = i >> 9, j = i & 511;
    float g[4];
#pragma unroll
    for (int q = 0; q < 4; q++) {
        float v = d_bs1[q * 512 + j];
#pragma unroll
        for (int kz = 0; kz < 4; kz++)
            v += __ldcg(d_gpart1 + kz * B_ * G4 + b * G4 + q * 512 + j);
        g[q] = v;
    }
    float c = sigf(g[1]) * d_c1[i] + sigf(g[0]) * tanhf(g[2]);
    float h = sigf(g[3]) * tanhf(c);
    d_c1[i] = c;
    __nv_bfloat16 hh, hl; split1(h, hh, hl);
    d_xbh[b * 1024 + 512 + j] = hh; d_xbl[b * 1024 + 512 + j] = hl;
    d_hist[((size_t)b * T_ + t) * H_ + j] = h;
}

__global__ __launch_bounds__(256) void recur_kernel(
    const int* __restrict__ batch_idx, const float* __restrict__ b_a,
    const float* __restrict__ W_fc, const float* __restrict__ b_fc,
    float* __restrict__ out)
{
    extern __shared__ __align__(16) char dsm[];
    __shared__ int sh_id;
    const int blk = blockIdx.x;
    const int tid = threadIdx.x;

    if (blk < NW) {
        // ----- worker: R7-exact 6-phase recurrence, barriers over 128 -----
        unsigned bar = 0;
        for (int t = 0; t < T_; t++) {
            if (blk < 64) {
                int n0 = (blk & 7) * 64, kz = blk >> 3;
                gemm64_hmma(d_xbh + 512, d_xbl + 512, 1024, kz * 64, 64,
                            d_Wah, d_Wal, 512, n0,
                            d_hppart + kz * B_ * H_, 512, dsm);
            }
            gbar(bar);
            if (blk < 64) attn_phase(blk, batch_idx, b_a, (AttnSh*)dsm);
            gbar(bar);
            {
                int n0 = (blk & 31) * 64, kz = blk >> 5;
                gemm64_hmma(d_xah, d_xal, 1024, kz * 256, 256,
                            d_W0h, d_W0l, 1024, n0,
                            d_gpart0 + kz * B_ * G4, G4, dsm);
            }
            gbar(bar);
            cell0_phase(blk * 256 + tid, t);
            gbar(bar);
            {
                int n0 = (blk & 31) * 64, kz = blk >> 5;
                gemm64_hmma(d_xbh, d_xbl, 1024, kz * 256, 256,
                            d_W1h, d_W1l, 1024, n0,
                            d_gpart1 + kz * B_ * G4, G4, dsm);
            }
            gbar(bar);
            cell1_phase(blk * 256 + tid, t);
            gbar(bar);
        }
    } else {
        // ----- consumer: overlap logits tiles on otherwise-idle SMs -----
        for (;;) {
            if (tid == 0) {
                int id = -1;
                if (ldvol(&g_cnt) < (unsigned)(6 * T_ * NW)) {   // recur not done
                    id = atomicAdd(&d_qhead, 1);
                    if (id < NQT) {
                        unsigned need = (unsigned)(6 * NW * (2 * (id / 250) + 2));
                        while (ldvol(&g_cnt) < need) { __nanosleep(128); }
                    }
                }
                sh_id = id;
            }
            __syncthreads();
            int id = sh_id;
            __syncthreads();
            if (id < 0 || id >= NQT) break;
            logits_tile128(id, W_fc, b_fc, out, dsm);
        }
    }
}

// ---- drain kernel: remaining queue tiles after the recurrence -----------
__global__ void __launch_bounds__(256, 1) logits_q(
    const float* __restrict__ W_fc, const float* __restrict__ b_fc,
    float* __restrict__ out)
{
    extern __shared__ __align__(16) char dsm[];
    __shared__ int sh_id;
    for (;;) {
        if (threadIdx.x == 0) sh_id = atomicAdd(&d_qhead, 1);
        __syncthreads();
        int id = sh_id;
        __syncthreads();
        if (id >= NQT) return;
        logits_tile128(id, W_fc, b_fc, out, dsm);
    }
}

// ---------------- one-time prep ------------------------------------------
__global__ void prep_kernel(
    const float* __restrict__ gf,
    const float* __restrict__ W_a,
    const float* __restrict__ W_ih0, const float* __restrict__ W_hh0,
    const float* __restrict__ b_ih0, const float* __restrict__ b_hh0,
    const float* __restrict__ W_ih1, const float* __restrict__ W_hh1,
    const float* __restrict__ b_ih1, const float* __restrict__ b_hh1,
    const int* __restrict__ captions)
{
    int i = blockIdx.x * blockDim.x + threadIdx.x;
    if (i < G4 * 1024) {
        int n = i >> 10, k = i & 1023;
        float w0 = (k < 512) ? W_ih0[n * 1024 + 512 + k] : W_hh0[n * 512 + (k - 512)];
        float w1 = (k < 512) ? W_ih1[n * 512 + k] : W_hh1[n * 512 + (k - 512)];
        __nv_bfloat16 h, l;
        split1(w0, h, l); d_W0h[i] = h; d_W0l[i] = l;
        split1(w1, h, l); d_W1h[i] = h; d_W1l[i] = l;
    }
    if (i < H_ * H_) {
        __nv_bfloat16 h, l;
        split1(W_a[i], h, l); d_Wah[i] = h; d_Wal[i] = l;
    }
    if (i < G4) { d_bs0[i] = b_ih0[i] + b_hh0[i]; d_bs1[i] = b_ih1[i] + b_hh1[i]; }
    if (i < T_ * B_) { int t = i / 64, b = i % 64; d_gidx[i] = captions[b * T_ + t]; }
    if (i < B_ * H_) {
        int b = i >> 9, j = i & 511;
        __nv_bfloat16 h, l;
        split1(gf[i], h, l);
        d_xah[b * 1024 + 512 + j] = h; d_xal[b * 1024 + 512 + j] = l;  // h0
        d_xbh[b * 1024 + 512 + j] = h; d_xbl[b * 1024 + 512 + j] = l;  // h1
        d_c0[i] = 0.f;
        d_c1[i] = 0.f;
    }
    if (i == 0) { g_cnt = 0u; d_qhead = 0; }
}

// ---------------- launch --------------------------------------------------
extern "C" void kernel_launch(void* const* d_in, const int* in_sizes, int n_in,
                              void* d_out, int out_size)
{
    const float* gf     = (const float*)d_in[0];
    const float* nf     = (const float*)d_in[1];
    const float* emb    = (const float*)d_in[2];
    const float* W_a    = (const float*)d_in[3];
    const float* b_a    = (const float*)d_in[4];
    const float* W_c    = (const float*)d_in[5];
    const float* b_c    = (const float*)d_in[6];
    const float* W_ih0  = (const float*)d_in[7];
    const float* W_hh0  = (const float*)d_in[8];
    const float* b_ih0  = (const float*)d_in[9];
    const float* b_hh0  = (const float*)d_in[10];
    const float* W_ih1  = (const float*)d_in[11];
    const float* W_hh1  = (const float*)d_in[12];
    const float* b_ih1  = (const float*)d_in[13];
    const float* b_hh1  = (const float*)d_in[14];
    const float* W_fc   = (const float*)d_in[15];
    const float* b_fc   = (const float*)d_in[16];
    const int* batch_idx = (const int*)d_in[17];
    const int* captions  = (const int*)d_in[18];
    float* out = (float*)d_out;

    float *node_proj, *embpart, *bs0;
    int* gidx;
    cudaGetSymbolAddress((void**)&node_proj, d_node_proj);
    cudaGetSymbolAddress((void**)&embpart,   d_embpart);
    cudaGetSymbolAddress((void**)&bs0,       d_bs0);
    cudaGetSymbolAddress((void**)&gidx,      d_gidx);

    cudaFuncSetAttribute(tgemm, cudaFuncAttributeMaxDynamicSharedMemorySize, TG_SMEM);
    cudaFuncSetAttribute(recur_kernel, cudaFuncAttributeMaxDynamicSharedMemorySize, RC_SMEM);
    cudaFuncSetAttribute(logits_q, cudaFuncAttributeMaxDynamicSharedMemorySize, TG_SMEM);

    // one-time prep: weight splits, bias sums, gather indices, state init
    prep_kernel<<<8192, 256>>>(gf, W_a, W_ih0, W_hh0, b_ih0, b_hh0,
                               W_ih1, W_hh1, b_ih1, b_hh1, captions);

    // node_proj = node_features @ W_c^T + b_c         [8192, 512]
    tgemm<<<dim3(NN_ / 128, H_ / 128), 256, TG_SMEM>>>(
        nf, H_, W_c, H_, node_proj, H_, b_c, H_, nullptr);

    // embpart = emb[captions] @ W_ih0[:, :512]^T + (b_ih0+b_hh0)   [1280, 2048]
    tgemm<<<dim3(T_ * B_ / 128, G4 / 128), 256, TG_SMEM>>>(
        emb, E_, W_ih0, 1024, embpart, G4, bs0, E_, gidx);

    // recurrence (128 worker CTAs) + overlapped logits consumers (20 CTAs)
    recur_kernel<<<NB, 256, RC_SMEM>>>(batch_idx, b_a, W_fc, b_fc, out);

    // drain remaining logits tiles with the full chip (same proven tile)
    logits_q<<<NB, 256, TG_SMEM>>>(W_fc, b_fc, out);
}

// round 17
// speedup vs baseline: 1.2221x; 1.0184x over previous
#include <cuda_runtime.h>
#include <cuda_bf16.h>
#include <math.h>
#include <stdint.h>

#define B_  64
#define T_  20
#define H_  512
#define E_  512
#define V_  32000
#define NN_ 8192
#define G4  2048   // 4*H
#define NB2 296    // oversubscribed grid (2 CTAs/SM)
#define NW  128    // worker CTAs participating in barriers
#define NQT 5000   // logits tiles: 10 t-pairs x 500 col-tiles of 64

// ---------------- static scratch (no allocations allowed) ----------------
__device__ float d_node_proj[NN_ * H_];
__device__ float d_embpart[T_ * B_ * G4];
__device__ float d_hist[B_ * T_ * H_];
__device__ float d_c0[B_ * H_];
__device__ float d_c1[B_ * H_];
__device__ float d_bs0[G4];
__device__ float d_bs1[G4];
__device__ int   d_gidx[T_ * B_];

__device__ __nv_bfloat16 d_Wah[H_ * H_], d_Wal[H_ * H_];
__device__ __nv_bfloat16 d_W0h[G4 * 1024], d_W0l[G4 * 1024];
__device__ __nv_bfloat16 d_W1h[G4 * 1024], d_W1l[G4 * 1024];
__device__ __nv_bfloat16 d_xah[B_ * 1024], d_xal[B_ * 1024];
__device__ __nv_bfloat16 d_xbh[B_ * 1024], d_xbl[B_ * 1024];

__device__ float d_hppart[8 * B_ * H_];
__device__ float d_gpart0[4 * B_ * G4];
__device__ float d_gpart1[4 * B_ * G4];
__device__ unsigned g_cnt;    // barrier arrivals (128 workers x 6/step)
__device__ int d_qhead;       // logits tile queue head

// ===================== helpers =====================
__device__ __forceinline__ uint32_t smem_u32(const void* p) {
    uint32_t a;
    asm("{ .reg .u64 t; cvta.to.shared.u64 t, %1; cvt.u32.u64 %0, t; }"
        : "=r"(a) : "l"(p));
    return a;
}
__device__ __forceinline__ void ldsm4(uint32_t* r, uint32_t addr) {
    asm volatile("ldmatrix.sync.aligned.m8n8.x4.shared.b16 {%0,%1,%2,%3}, [%4];"
                 : "=r"(r[0]), "=r"(r[1]), "=r"(r[2]), "=r"(r[3]) : "r"(addr));
}
__device__ __forceinline__ void ldsm2(uint32_t* r, uint32_t addr) {
    asm volatile("ldmatrix.sync.aligned.m8n8.x2.shared.b16 {%0,%1}, [%2];"
                 : "=r"(r[0]), "=r"(r[1]) : "r"(addr));
}
__device__ __forceinline__ void mma_bf16(float* d, const uint32_t* a, const uint32_t* b) {
    asm volatile(
        "mma.sync.aligned.m16n8k16.row.col.f32.bf16.bf16.f32 "
        "{%0,%1,%2,%3}, {%4,%5,%6,%7}, {%8,%9}, {%0,%1,%2,%3};"
        : "+f"(d[0]), "+f"(d[1]), "+f"(d[2]), "+f"(d[3])
        : "r"(a[0]), "r"(a[1]), "r"(a[2]), "r"(a[3]), "r"(b[0]), "r"(b[1]));
}
__device__ __forceinline__ unsigned ldvol(const unsigned* p) {
    unsigned v;
    asm volatile("ld.global.cg.u32 %0, [%1];" : "=r"(v) : "l"(p) : "memory");
    return v;
}
__device__ __forceinline__ void split1(float v, __nv_bfloat16& h, __nv_bfloat16& l) {
    h = __float2bfloat16(v);
    l = __float2bfloat16(v - __bfloat162float(h));
}
__device__ __forceinline__ void split4(float4 a, uint2& hi, uint2& lo) {
    __nv_bfloat16 h0, h1, h2, h3, l0, l1, l2, l3;
    split1(a.x, h0, l0); split1(a.y, h1, l1);
    split1(a.z, h2, l2); split1(a.w, h3, l3);
    __nv_bfloat162 ph = __nv_bfloat162(h0, h1), qh = __nv_bfloat162(h2, h3);
    __nv_bfloat162 pl = __nv_bfloat162(l0, l1), ql = __nv_bfloat162(l2, l3);
    hi = make_uint2(*(uint32_t*)&ph, *(uint32_t*)&qh);
    lo = make_uint2(*(uint32_t*)&pl, *(uint32_t*)&ql);
}
__device__ __forceinline__ float sigf(float x) { return 1.f / (1.f + expf(-x)); }

// ========== big split-bf16 HMMA GEMM (validated R3/R4) ===================
#define TG_STAGE 40960
#define TG_SMEM  (2 * TG_STAGE)

__global__ void __launch_bounds__(256, 1) tgemm(
    const float* __restrict__ A, int lda,
    const float* __restrict__ Bw, int ldb,
    float* __restrict__ C, int ldc,
    const float* __restrict__ bias,
    int K, const int* __restrict__ gidx)
{
    extern __shared__ char sm[];
    const uint32_t sbase = smem_u32(sm);
    const int tid = threadIdx.x;
    const int lane = tid & 31, wid = tid >> 5;
    const int wm = wid & 1, wn = wid >> 1;
    const int m0 = blockIdx.x * 128, n0 = blockIdx.y * 128;
    const int lrow = tid >> 3;
    const int c4 = (tid & 7) << 2;
    const uint32_t aLane = (((uint32_t)(lane & 15) * 40u) + ((lane >> 4) * 8u)) * 2u;
    const uint32_t bLane = (((uint32_t)(lane & 7) * 40u) + (((lane >> 3) & 1) * 8u)) * 2u;

    float acc[4][4][4];
#pragma unroll
    for (int i = 0; i < 4; i++)
#pragma unroll
        for (int j = 0; j < 4; j++)
#pragma unroll
            for (int q = 0; q < 4; q++) acc[i][j][q] = 0.f;

    const int nch = K >> 5;
    float4 ga[4], gb[4];
#pragma unroll
    for (int v = 0; v < 4; v++) {
        int row = lrow + v * 32;
        int gr = gidx ? gidx[m0 + row] : (m0 + row);
        ga[v] = *(const float4*)(A + (size_t)gr * lda + c4);
        gb[v] = *(const float4*)(Bw + (size_t)(n0 + row) * ldb + c4);
    }
#pragma unroll
    for (int v = 0; v < 4; v++) {
        int row = lrow + v * 32;
        uint32_t off = ((uint32_t)row * 40u + (uint32_t)c4) * 2u;
        uint2 hi, lo;
        split4(ga[v], hi, lo);
        *(uint2*)(sm + off) = hi;
        *(uint2*)(sm + 10240 + off) = lo;
        split4(gb[v], hi, lo);
        *(uint2*)(sm + 20480 + off) = hi;
        *(uint2*)(sm + 30720 + off) = lo;
    }
    __syncthreads();

    for (int ich = 0; ich < nch; ich++) {
        const bool pf = (ich + 1 < nch);
        if (pf) {
            const int kb = (ich + 1) << 5;
#pragma unroll
            for (int v = 0; v < 4; v++) {
                int row = lrow + v * 32;
                int gr = gidx ? gidx[m0 + row] : (m0 + row);
                ga[v] = *(const float4*)(A + (size_t)gr * lda + kb + c4);
                gb[v] = *(const float4*)(Bw + (size_t)(n0 + row) * ldb + kb + c4);
            }
        }
        const uint32_t st = sbase + (uint32_t)(ich & 1) * TG_STAGE;
#pragma unroll
        for (int kk = 0; kk < 2; kk++) {
            uint32_t Ah[4][4], Al[4][4], Bh[4][2], Bl[4][2];
#pragma unroll
            for (int ma = 0; ma < 4; ma++) {
                uint32_t ad = st + (uint32_t)(wm * 64 + ma * 16) * 80u + aLane + kk * 32u;
                ldsm4(Ah[ma], ad);
                ldsm4(Al[ma], ad + 10240u);
            }
#pragma unroll
            for (int na = 0; na < 4; na++) {
                uint32_t bd = st + 20480u + (uint32_t)(wn * 32 + na * 8) * 80u + bLane + kk * 32u;
                ldsm2(Bh[na], bd);
                ldsm2(Bl[na], bd + 10240u);
            }
#pragma unroll
            for (int ma = 0; ma < 4; ma++)
#pragma unroll
                for (int na = 0; na < 4; na++) {
                    mma_bf16(acc[ma][na], Ah[ma], Bh[na]);
                    mma_bf16(acc[ma][na], Al[ma], Bh[na]);
                    mma_bf16(acc[ma][na], Ah[ma], Bl[na]);
                }
        }
        if (pf) {
            char* dstS = sm + ((ich + 1) & 1) * TG_STAGE;
#pragma unroll
            for (int v = 0; v < 4; v++) {
                int row = lrow + v * 32;
                uint32_t off = ((uint32_t)row * 40u + (uint32_t)c4) * 2u;
                uint2 hi, lo;
                split4(ga[v], hi, lo);
                *(uint2*)(dstS + off) = hi;
                *(uint2*)(dstS + 10240 + off) = lo;
                split4(gb[v], hi, lo);
                *(uint2*)(dstS + 20480 + off) = hi;
                *(uint2*)(dstS + 30720 + off) = lo;
            }
        }
        __syncthreads();
    }

    const int g = lane >> 2, t = lane & 3;
#pragma unroll
    for (int ma = 0; ma < 4; ma++) {
        int r = m0 + wm * 64 + ma * 16 + g;
#pragma unroll
        for (int na = 0; na < 4; na++) {
            int c = n0 + wn * 32 + na * 8 + 2 * t;
            float2 bb = make_float2(0.f, 0.f);
            if (bias) bb = *(const float2*)(bias + c);
            *(float2*)(C + (size_t)r * ldc + c) =
                make_float2(acc[ma][na][0] + bb.x, acc[ma][na][1] + bb.y);
            *(float2*)(C + (size_t)(r + 8) * ldc + c) =
                make_float2(acc[ma][na][2] + bb.x, acc[ma][na][3] + bb.y);
        }
    }
}

// ===== logits queue tile: 128 rows (b, t-pair) x 64 vocab cols, K=512 ====
// R14-validated n64 tile body + QROW gather. regs fit 2 CTAs/SM.
// Stage: Ah(10240) Al(10240) Bh(5120) Bl(5120) = 30720 B; 2 stages.
#define TN_STAGE 30720
#define TN_SMEM  (2 * TN_STAGE)

__device__ void logits_tile64(
    int id, const float* __restrict__ W_fc, const float* __restrict__ b_fc,
    float* __restrict__ out, char* sm)
{
    const uint32_t sbase = smem_u32(sm);
    const int tid = threadIdx.x;
    const int lane = tid & 31, wid = tid >> 5;
    const int wm = wid & 1, wn = wid >> 1;     // 2 (M) x 4 (N)
    const int tp2 = (id / 500) * 2;
    const int n0 = (id % 500) * 64;
    const int arow = tid >> 2;                 // 0..63 (+64)
    const int ac = (tid & 3) << 3;             // 0,8,16,24
    const int brow = tid >> 3;                 // 0..31 (+32)
    const int bc = (tid & 7) << 2;             // 0..28 by 4
    const uint32_t aLane = (((uint32_t)(lane & 15) * 40u) + ((lane >> 4) * 8u)) * 2u;
    const uint32_t bLane = (((uint32_t)(lane & 7) * 40u) + (((lane >> 3) & 1) * 8u)) * 2u;

#define QROW(r) (((r) >> 1) * T_ + tp2 + ((r) & 1))

    float acc[4][2][4];
#pragma unroll
    for (int i = 0; i < 4; i++)
#pragma unroll
        for (int j = 0; j < 2; j++)
#pragma unroll
            for (int q = 0; q < 4; q++) acc[i][j][q] = 0.f;

    float4 ga[2][2], gb[2];

#define TN_LOAD(kb)                                                               \
    do {                                                                          \
        _Pragma("unroll")                                                         \
        for (int v = 0; v < 2; v++) {                                             \
            const float* ap = d_hist + (size_t)QROW(arow + v * 64) * 512 + (kb) + ac; \
            ga[v][0] = __ldcg((const float4*)ap);                                 \
            ga[v][1] = __ldcg((const float4*)(ap + 4));                           \
            gb[v] = *(const float4*)(W_fc + (size_t)(n0 + brow + v * 32) * 512 + (kb) + bc); \
        }                                                                         \
    } while (0)

#define TN_STORE(dst)                                                             \
    do {                                                                          \
        _Pragma("unroll")                                                         \
        for (int v = 0; v < 2; v++) {                                             \
            uint2 hi, lo;                                                         \
            uint32_t ao = ((uint32_t)(arow + v * 64) * 40u + (uint32_t)ac) * 2u;  \
            split4(ga[v][0], hi, lo);                                             \
            *(uint2*)((dst) + ao) = hi;                                           \
            *(uint2*)((dst) + 10240 + ao) = lo;                                   \
            split4(ga[v][1], hi, lo);                                             \
            *(uint2*)((dst) + ao + 8) = hi;                                       \
            *(uint2*)((dst) + 10240 + ao + 8) = lo;                               \
            uint32_t bo = ((uint32_t)(brow + v * 32) * 40u + (uint32_t)bc) * 2u;  \
            split4(gb[v], hi, lo);                                                \
            *(uint2*)((dst) + 20480 + bo) = hi;                                   \
            *(uint2*)((dst) + 25600 + bo) = lo;                                   \
        }                                                                         \
    } while (0)

    TN_LOAD(0);
    TN_STORE(sm);
    __syncthreads();

    for (int ich = 0; ich < 16; ich++) {
        const bool pf = (ich + 1 < 16);
        if (pf) TN_LOAD((ich + 1) << 5);
        const uint32_t st = sbase + (uint32_t)(ich & 1) * TN_STAGE;
#pragma unroll
        for (int kk = 0; kk < 2; kk++) {
            uint32_t Ah[4][4], Al[4][4], Bh[2][2], Bl[2][2];
#pragma unroll
            for (int ma = 0; ma < 4; ma++) {
                uint32_t ad = st + (uint32_t)(wm * 64 + ma * 16) * 80u + aLane + kk * 32u;
                ldsm4(Ah[ma], ad);
                ldsm4(Al[ma], ad + 10240u);
            }
#pragma unroll
            for (int na = 0; na < 2; na++) {
                uint32_t bd = st + 20480u + (uint32_t)(wn * 16 + na * 8) * 80u + bLane + kk * 32u;
                ldsm2(Bh[na], bd);
                ldsm2(Bl[na], bd + 5120u);
            }
#pragma unroll
            for (int ma = 0; ma < 4; ma++)
#pragma unroll
                for (int na = 0; na < 2; na++) {
                    mma_bf16(acc[ma][na], Ah[ma], Bh[na]);
                    mma_bf16(acc[ma][na], Al[ma], Bh[na]);
                    mma_bf16(acc[ma][na], Ah[ma], Bl[na]);
                }
        }
        if (pf) TN_STORE(sm + ((ich + 1) & 1) * TN_STAGE);
        __syncthreads();
    }
#undef TN_LOAD
#undef TN_STORE

    const int g = lane >> 2, qt = lane & 3;
#pragma unroll
    for (int ma = 0; ma < 4; ma++) {
        int rl = wm * 64 + ma * 16 + g;
#pragma unroll
        for (int na = 0; na < 2; na++) {
            int c = n0 + wn * 16 + na * 8 + 2 * qt;
            float2 bb = *(const float2*)(b_fc + c);
            *(float2*)(out + (size_t)QROW(rl) * V_ + c) =
                make_float2(acc[ma][na][0] + bb.x, acc[ma][na][1] + bb.y);
            *(float2*)(out + (size_t)QROW(rl + 8) * V_ + c) =
                make_float2(acc[ma][na][2] + bb.x, acc[ma][na][3] + bb.y);
        }
    }
#undef QROW
}

// ==================== persistent recurrence kernel =======================
struct AttnSh {
    float hp[512];
    float ctx[8][512];
    float m[8], s[8];
};
#define RC_STAGE 36864u
#define RC_SMEM  (2 * 36864)   // 73728 B; 2 CTAs/SM fit

// barrier over 128 worker CTAs only
__device__ __forceinline__ void gbar(unsigned& bar)
{
    bar += NW;
    __threadfence();
    __syncthreads();
    if (threadIdx.x == 0) {
        atomicAdd(&g_cnt, 1u);
        volatile unsigned* pc = &g_cnt;
        while (*pc < bar) { __nanosleep(64); }
    }
    __syncthreads();
}

__device__ __forceinline__ void gemm64_hmma(
    const __nv_bfloat16* __restrict__ Agh, const __nv_bfloat16* __restrict__ Agl, int lda,
    int kbeg, int klen,
    const __nv_bfloat16* __restrict__ Bgh, const __nv_bfloat16* __restrict__ Bgl,
    int ldb, int n0,
    float* __restrict__ Cp, int ldc, char* sb)
{
    const uint32_t ub = smem_u32(sb);
    const int tid = threadIdx.x, lane = tid & 31, wid = tid >> 5;
    const int wm = wid & 1, wn = wid >> 1;
    const int grow = tid >> 2;
    const int gc0 = (tid & 3) << 3;
    const uint32_t aLane = (uint32_t)((lane & 15) * 144 + (lane >> 4) * 16);
    const uint32_t bLane = (uint32_t)((lane & 7) * 144 + ((lane >> 3) & 1) * 16);

    float acc[2][2][4];
#pragma unroll
    for (int i = 0; i < 2; i++)
#pragma unroll
        for (int j = 0; j < 2; j++)
#pragma unroll
            for (int q = 0; q < 4; q++) acc[i][j][q] = 0.f;

    const int nch = klen >> 6;
    uint4 rah0, rah1, ral0, ral1, rbh0, rbh1, rbl0, rbl1;

#define RC_LOAD(kb)                                                              \
    do {                                                                         \
        const __nv_bfloat16* ap = Agh + (size_t)grow * lda + (kb) + gc0;         \
        const __nv_bfloat16* alp = Agl + (size_t)grow * lda + (kb) + gc0;        \
        const __nv_bfloat16* bp = Bgh + (size_t)(n0 + grow) * ldb + (kb) + gc0;  \
        const __nv_bfloat16* blp = Bgl + (size_t)(n0 + grow) * ldb + (kb) + gc0; \
        rah0 = __ldcg((const uint4*)ap);  rah1 = __ldcg((const uint4*)(ap + 32));  \
        ral0 = __ldcg((const uint4*)alp); ral1 = __ldcg((const uint4*)(alp + 32)); \
        rbh0 = *(const uint4*)bp;         rbh1 = *(const uint4*)(bp + 32);       \
        rbl0 = *(const uint4*)blp;        rbl1 = *(const uint4*)(blp + 32);      \
    } while (0)

#define RC_STORE(stg)                                                            \
    do {                                                                         \
        uint32_t so = (stg) + (uint32_t)(grow * 144 + gc0 * 2);                  \
        *(uint4*)(sb + so) = rah0;          *(uint4*)(sb + so + 64) = rah1;      \
        *(uint4*)(sb + 9216 + so) = ral0;   *(uint4*)(sb + 9216 + so + 64) = ral1; \
        *(uint4*)(sb + 18432 + so) = rbh0;  *(uint4*)(sb + 18432 + so + 64) = rbh1; \
        *(uint4*)(sb + 27648 + so) = rbl0;  *(uint4*)(sb + 27648 + so + 64) = rbl1; \
    } while (0)

    RC_LOAD(kbeg);
    RC_STORE(0u);
    __syncthreads();

    for (int ich = 0; ich < nch; ich++) {
        const bool pf = (ich + 1 < nch);
        if (pf) RC_LOAD(kbeg + ((ich + 1) << 6));
        const uint32_t st = (uint32_t)(ich & 1) * RC_STAGE;
#pragma unroll
        for (int kk = 0; kk < 4; kk++) {
            uint32_t Ahf[2][4], Alf[2][4], Bhf[2][2], Blf[2][2];
#pragma unroll
            for (int ma = 0; ma < 2; ma++) {
                uint32_t ro = st + (uint32_t)(wm * 32 + ma * 16) * 144u + aLane + kk * 32u;
                ldsm4(Ahf[ma], ub + ro);
                ldsm4(Alf[ma], ub + 9216u + ro);
            }
#pragma unroll
            for (int na = 0; na < 2; na++) {
                uint32_t co = st + 18432u + (uint32_t)(wn * 16 + na * 8) * 144u + bLane + kk * 32u;
                ldsm2(Bhf[na], ub + co);
                ldsm2(Blf[na], ub + 9216u + co);
            }
#pragma unroll
            for (int ma = 0; ma < 2; ma++)
#pragma unroll
                for (int na = 0; na < 2; na++) {
                    mma_bf16(acc[ma][na], Ahf[ma], Bhf[na]);
                    mma_bf16(acc[ma][na], Alf[ma], Bhf[na]);
                    mma_bf16(acc[ma][na], Ahf[ma], Blf[na]);
                }
        }
        if (pf) RC_STORE((uint32_t)((ich + 1) & 1) * RC_STAGE);
        __syncthreads();
    }
#undef RC_LOAD
#undef RC_STORE

    const int gq = lane >> 2, qt = lane & 3;
#pragma unroll
    for (int ma = 0; ma < 2; ma++) {
        int r = wm * 32 + ma * 16 + gq;
#pragma unroll
        for (int na = 0; na < 2; na++) {
            int c = n0 + wn * 16 + na * 8 + qt * 2;
            *(float2*)(Cp + (size_t)r * ldc + c) =
                make_float2(acc[ma][na][0], acc[ma][na][1]);
            *(float2*)(Cp + (size_t)(r + 8) * ldc + c) =
                make_float2(acc[ma][na][2], acc[ma][na][3]);
        }
    }
}

__device__ __forceinline__ int lowbound(const int* __restrict__ a, int n, int v)
{
    int lo = 0, hi = n;
    while (lo < hi) { int mid = (lo + hi) >> 1; if (a[mid] < v) lo = mid + 1; else hi = mid; }
    return lo;
}

__device__ __forceinline__ void attn_phase(int b, const int* __restrict__ batch_idx,
                                           const float* __restrict__ b_a, AttnSh* s)
{
    const int tid = threadIdx.x, lane = tid & 31, w = tid >> 5;
    for (int j = tid; j < 512; j += 256) {
        float v = b_a[j];
#pragma unroll
        for (int kz = 0; kz < 8; kz++)
            v += __ldcg(d_hppart + kz * B_ * H_ + b * 512 + j);
        s->hp[j] = v;
    }
    __syncthreads();

    float hpreg[16];
#pragma unroll
    for (int i = 0; i < 4; i++) {
        float4 t4 = *(const float4*)&s->hp[lane * 16 + i * 4];
        hpreg[i * 4 + 0] = t4.x; hpreg[i * 4 + 1] = t4.y;
        hpreg[i * 4 + 2] = t4.z; hpreg[i * 4 + 3] = t4.w;
    }

    const int s0 = lowbound(batch_idx, NN_, b);
    const int s1 = lowbound(batch_idx, NN_, b + 1);

    float m = -INFINITY, ssum = 0.f;
    float ctx[16];
#pragma unroll
    for (int i = 0; i < 16; i++) ctx[i] = 0.f;

#pragma unroll 2
    for (int n = s0 + w; n < s1; n += 8) {
        const float4* np = (const float4*)(d_node_proj + (size_t)n * 512 + lane * 16);
        float4 a0 = np[0], a1 = np[1], a2 = np[2], a3 = np[3];
        float v[16] = {a0.x, a0.y, a0.z, a0.w, a1.x, a1.y, a1.z, a1.w,
                       a2.x, a2.y, a2.z, a2.w, a3.x, a3.y, a3.z, a3.w};
        float p = 0.f;
#pragma unroll
        for (int i = 0; i < 16; i++) p = fmaf(v[i], hpreg[i], p);
#pragma unroll
        for (int o = 16; o > 0; o >>= 1) p += __shfl_xor_sync(0xffffffffu, p, o);
        float mn = fmaxf(m, p);
        float scale = expf(m - mn);
        float e = expf(p - mn);
        ssum = ssum * scale + e;
#pragma unroll
        for (int i = 0; i < 16; i++) ctx[i] = ctx[i] * scale + e * v[i];
        m = mn;
    }
#pragma unroll
    for (int i = 0; i < 4; i++)
        *(float4*)&s->ctx[w][lane * 16 + i * 4] =
            make_float4(ctx[i * 4], ctx[i * 4 + 1], ctx[i * 4 + 2], ctx[i * 4 + 3]);
    if (lane == 0) { s->m[w] = m; s->s[w] = ssum; }
    __syncthreads();

    float M = -INFINITY;
#pragma unroll
    for (int ww = 0; ww < 8; ww++) M = fmaxf(M, s->m[ww]);
    if (M == -INFINITY) {
        for (int j = tid; j < 512; j += 256) {
            __nv_bfloat16 hh, hl; split1(0.f, hh, hl);
            d_xah[b * 1024 + j] = hh; d_xal[b * 1024 + j] = hl;
        }
    } else {
        float stot = 0.f;
        float ew[8];
#pragma unroll
        for (int ww = 0; ww < 8; ww++) { ew[ww] = expf(s->m[ww] - M); stot += s->s[ww] * ew[ww]; }
        float inv = 1.f / stot;
        for (int j = tid; j < 512; j += 256) {
            float num = 0.f;
#pragma unroll
            for (int ww = 0; ww < 8; ww++) num = fmaf(s->ctx[ww][j], ew[ww], num);
            float v = num * inv;
            __nv_bfloat16 hh, hl; split1(v, hh, hl);
            d_xah[b * 1024 + j] = hh; d_xal[b * 1024 + j] = hl;
        }
    }
}

__device__ __forceinline__ void cell0_phase(int i, int t)
{
    int b = i >> 9, j = i & 511;
    const float* ep = d_embpart + (size_t)t * B_ * G4 + b * G4 + j;
    float g[4];
#pragma unroll
    for (int q = 0; q < 4; q++) {
        float v = ep[q * 512];
#pragma unroll
        for (int kz = 0; kz < 4; kz++)
            v += __ldcg(d_gpart0 + kz * B_ * G4 + b * G4 + q * 512 + j);
        g[q] = v;
    }
    float c = sigf(g[1]) * d_c0[i] + sigf(g[0]) * tanhf(g[2]);
    float h = sigf(g[3]) * tanhf(c);
    d_c0[i] = c;
    __nv_bfloat16 hh, hl; split1(h, hh, hl);
    d_xah[b * 1024 + 512 + j] = hh; d_xal[b * 1024 + 512 + j] = hl;
    d_xbh[b * 1024 + j] = hh;       d_xbl[b * 1024 + j] = hl;
}

__device__ __forceinline__ void cell1_phase(int i, int t)
{
    int b = i >> 9, j = i & 511;
    float g[4];
#pragma unroll
    for (int q = 0; q < 4; q++) {
        float v = d_bs1[q * 512 + j];
#pragma unroll
        for (int kz = 0; kz < 4; kz++)
            v += __ldcg(d_gpart1 + kz * B_ * G4 + b * G4 + q * 512 + j);
        g[q] = v;
    }
    float c = sigf(g[1]) * d_c1[i] + sigf(g[0]) * tanhf(g[2]);
    float h = sigf(g[3]) * tanhf(c);
    d_c1[i] = c;
    __nv_bfloat16 hh, hl; split1(h, hh, hl);
    d_xbh[b * 1024 + 512 + j] = hh; d_xbl[b * 1024 + 512 + j] = hl;
    d_hist[((size_t)b * T_ + t) * H_ + j] = h;
}

__global__ void __launch_bounds__(256, 2) recur_kernel(
    const int* __restrict__ batch_idx, const float* __restrict__ b_a,
    const float* __restrict__ W_fc, const float* __restrict__ b_fc,
    float* __restrict__ out)
{
    extern __shared__ __align__(16) char dsm[];
    __shared__ int sh_id;
    const int blk = blockIdx.x;
    const int tid = threadIdx.x;

    if (blk < NW) {
        // ----- worker: R7-exact 6-phase recurrence, barriers over 128 -----
        unsigned bar = 0;
        for (int t = 0; t < T_; t++) {
            if (blk < 64) {
                int n0 = (blk & 7) * 64, kz = blk >> 3;
                gemm64_hmma(d_xbh + 512, d_xbl + 512, 1024, kz * 64, 64,
                            d_Wah, d_Wal, 512, n0,
                            d_hppart + kz * B_ * H_, 512, dsm);
            }
            gbar(bar);
            if (blk < 64) attn_phase(blk, batch_idx, b_a, (AttnSh*)dsm);
            gbar(bar);
            {
                int n0 = (blk & 31) * 64, kz = blk >> 5;
                gemm64_hmma(d_xah, d_xal, 1024, kz * 256, 256,
                            d_W0h, d_W0l, 1024, n0,
                            d_gpart0 + kz * B_ * G4, G4, dsm);
            }
            gbar(bar);
            cell0_phase(blk * 256 + tid, t);
            gbar(bar);
            {
                int n0 = (blk & 31) * 64, kz = blk >> 5;
                gemm64_hmma(d_xbh, d_xbl, 1024, kz * 256, 256,
                            d_W1h, d_W1l, 1024, n0,
                            d_gpart1 + kz * B_ * G4, G4, dsm);
            }
            gbar(bar);
            cell1_phase(blk * 256 + tid, t);
            gbar(bar);
        }
    } else {
        // ----- consumer (168 CTAs, co-resident): logits tiles -----
        for (;;) {
            if (tid == 0) {
                int id = -1;
                if (ldvol(&g_cnt) < (unsigned)(6 * T_ * NW)) {   // recur not done
                    id = atomicAdd(&d_qhead, 1);
                    if (id < NQT) {
                        unsigned need = (unsigned)(6 * NW * (2 * (id / 500) + 2));
                        while (ldvol(&g_cnt) < need) { __nanosleep(128); }
                    }
                }
                sh_id = id;
            }
            __syncthreads();
            int id = sh_id;
            __syncthreads();
            if (id < 0 || id >= NQT) break;
            logits_tile64(id, W_fc, b_fc, out, dsm);
        }
    }
}

// ---- drain kernel: remaining queue tiles after the recurrence -----------
__global__ void __launch_bounds__(256, 2) logits_q(
    const float* __restrict__ W_fc, const float* __restrict__ b_fc,
    float* __restrict__ out)
{
    extern __shared__ __align__(16) char dsm[];
    __shared__ int sh_id;
    for (;;) {
        if (threadIdx.x == 0) sh_id = atomicAdd(&d_qhead, 1);
        __syncthreads();
        int id = sh_id;
        __syncthreads();
        if (id >= NQT) return;
        logits_tile64(id, W_fc, b_fc, out, dsm);
    }
}

// ---------------- one-time prep ------------------------------------------
__global__ void prep_kernel(
    const float* __restrict__ gf,
    const float* __restrict__ W_a,
    const float* __restrict__ W_ih0, const float* __restrict__ W_hh0,
    const float* __restrict__ b_ih0, const float* __restrict__ b_hh0,
    const float* __restrict__ W_ih1, const float* __restrict__ W_hh1,
    const float* __restrict__ b_ih1, const float* __restrict__ b_hh1,
    const int* __restrict__ captions)
{
    int i = blockIdx.x * blockDim.x + threadIdx.x;
    if (i < G4 * 1024) {
        int n = i >> 10, k = i & 1023;
        float w0 = (k < 512) ? W_ih0[n * 1024 + 512 + k] : W_hh0[n * 512 + (k - 512)];
        float w1 = (k < 512) ? W_ih1[n * 512 + k] : W_hh1[n * 512 + (k - 512)];
        __nv_bfloat16 h, l;
        split1(w0, h, l); d_W0h[i] = h; d_W0l[i] = l;
        split1(w1, h, l); d_W1h[i] = h; d_W1l[i] = l;
    }
    if (i < H_ * H_) {
        __nv_bfloat16 h, l;
        split1(W_a[i], h, l); d_Wah[i] = h; d_Wal[i] = l;
    }
    if (i < G4) { d_bs0[i] = b_ih0[i] + b_hh0[i]; d_bs1[i] = b_ih1[i] + b_hh1[i]; }
    if (i < T_ * B_) { int t = i / 64, b = i % 64; d_gidx[i] = captions[b * T_ + t]; }
    if (i < B_ * H_) {
        int b = i >> 9, j = i & 511;
        __nv_bfloat16 h, l;
        split1(gf[i], h, l);
        d_xah[b * 1024 + 512 + j] = h; d_xal[b * 1024 + 512 + j] = l;  // h0
        d_xbh[b * 1024 + 512 + j] = h; d_xbl[b * 1024 + 512 + j] = l;  // h1
        d_c0[i] = 0.f;
        d_c1[i] = 0.f;
    }
    if (i == 0) { g_cnt = 0u; d_qhead = 0; }
}

// ---------------- launch --------------------------------------------------
extern "C" void kernel_launch(void* const* d_in, const int* in_sizes, int n_in,
                              void* d_out, int out_size)
{
    const float* gf     = (const float*)d_in[0];
    const float* nf     = (const float*)d_in[1];
    const float* emb    = (const float*)d_in[2];
    const float* W_a    = (const float*)d_in[3];
    const float* b_a    = (const float*)d_in[4];
    const float* W_c    = (const float*)d_in[5];
    const float* b_c    = (const float*)d_in[6];
    const float* W_ih0  = (const float*)d_in[7];
    const float* W_hh0  = (const float*)d_in[8];
    const float* b_ih0  = (const float*)d_in[9];
    const float* b_hh0  = (const float*)d_in[10];
    const float* W_ih1  = (const float*)d_in[11];
    const float* W_hh1  = (const float*)d_in[12];
    const float* b_ih1  = (const float*)d_in[13];
    const float* b_hh1  = (const float*)d_in[14];
    const float* W_fc   = (const float*)d_in[15];
    const float* b_fc   = (const float*)d_in[16];
    const int* batch_idx = (const int*)d_in[17];
    const int* captions  = (const int*)d_in[18];
    float* out = (float*)d_out;

    float *node_proj, *embpart, *bs0;
    int* gidx;
    cudaGetSymbolAddress((void**)&node_proj, d_node_proj);
    cudaGetSymbolAddress((void**)&embpart,   d_embpart);
    cudaGetSymbolAddress((void**)&bs0,       d_bs0);
    cudaGetSymbolAddress((void**)&gidx,      d_gidx);

    cudaFuncSetAttribute(tgemm, cudaFuncAttributeMaxDynamicSharedMemorySize, TG_SMEM);
    cudaFuncSetAttribute(recur_kernel, cudaFuncAttributeMaxDynamicSharedMemorySize, RC_SMEM);
    cudaFuncSetAttribute(logits_q, cudaFuncAttributeMaxDynamicSharedMemorySize, TN_SMEM);

    // one-time prep: weight splits, bias sums, gather indices, state init
    prep_kernel<<<8192, 256>>>(gf, W_a, W_ih0, W_hh0, b_ih0, b_hh0,
                               W_ih1, W_hh1, b_ih1, b_hh1, captions);

    // node_proj = node_features @ W_c^T + b_c         [8192, 512]
    tgemm<<<dim3(NN_ / 128, H_ / 128), 256, TG_SMEM>>>(
        nf, H_, W_c, H_, node_proj, H_, b_c, H_, nullptr);

    // embpart = emb[captions] @ W_ih0[:, :512]^T + (b_ih0+b_hh0)   [1280, 2048]
    tgemm<<<dim3(T_ * B_ / 128, G4 / 128), 256, TG_SMEM>>>(
        emb, E_, W_ih0, 1024, embpart, G4, bs0, E_, gidx);

    // recurrence (128 workers) + co-resident logits consumers (168 CTAs)
    recur_kernel<<<NB2, 256, RC_SMEM>>>(batch_idx, b_a, W_fc, b_fc, out);

    // drain any remaining logits tiles
    logits_q<<<NB2, 256, TN_SMEM>>>(W_fc, b_fc, out);
}